// round 7
// baseline (speedup 1.0000x reference)
#include <cuda_runtime.h>
#include <cuda_bf16.h>
#include <cstdint>
#include <math.h>

// ---------------------------------------------------------------------------
// Problem constants
//   B=2, H=W=256, C=192, HEADS=6, HEAD_DIM=32, WS=8, PW=4, HIDDEN=768
//   NTOK = B*H*W = 131072 tokens
// ---------------------------------------------------------------------------
#define NTOK   131072
#define QKVLD  288      // 192 (q) + 96 (kv) per token, bf16
#define HID    768
#define ATT_SCALE 0.17677669529663688f   // 32^-0.5

// Scratch (static device allocations — no cudaMalloc allowed)
__device__ __align__(16) __nv_bfloat16 g_xn  [(size_t)NTOK * 192]; // LN out
__device__ __align__(16) __nv_bfloat16 g_qkvb[(size_t)NTOK * QKVLD];
__device__ __align__(16) __nv_bfloat16 g_aw  [(size_t)NTOK * 192]; // attn out
__device__ __align__(16) float         g_x2  [(size_t)NTOK * 192]; // resid
__device__ __align__(16) __nv_bfloat16 g_h1  [(size_t)NTOK * HID]; // gelu(fc1)
__device__ __align__(16) __nv_bfloat16 g_h   [(size_t)NTOK * HID]; // ffn hidden
// bf16 weights: wqkv (192x288) | wproj | w1f | w2f
#define WB_WQKV  0
#define WB_WPROJ 55296
#define WB_W1F   92160
#define WB_W2F   239616
__device__ __align__(16) __nv_bfloat16 g_wb[387072];
__device__ __align__(16) float g_bqkv[288];

__device__ __forceinline__ float gelu_f(float v) {
    return 0.5f * v * (1.0f + erff(v * 0.70710678118654752440f));
}

// ---------------------------------------------------------------------------
// Weight prep: concat wq|wkv into 192x288 + convert all weights to bf16
// ---------------------------------------------------------------------------
__global__ __launch_bounds__(256) void prep_kernel(
    const float* __restrict__ wq, const float* __restrict__ wkv,
    const float* __restrict__ wproj, const float* __restrict__ w1f,
    const float* __restrict__ w2f, __nv_bfloat16* __restrict__ wb)
{
    int i = blockIdx.x * 256 + threadIdx.x;
    if (i >= 387072) return;
    float v;
    if (i < 55296) {
        int row = i / 288, col = i - row * 288;
        v = (col < 192) ? wq[row * 192 + col] : wkv[row * 96 + col - 192];
    } else if (i < 92160) {
        v = wproj[i - 55296];
    } else if (i < 239616) {
        v = w1f[i - 92160];
    } else {
        v = w2f[i - 239616];
    }
    wb[i] = __float2bfloat16(v);
}

__global__ void biasprep_kernel(const float* __restrict__ bq,
                                const float* __restrict__ bkv,
                                float* __restrict__ bqkv)
{
    int i = threadIdx.x;
    if (i < 288) bqkv[i] = (i < 192) ? bq[i] : bkv[i - 192];
}

// ---------------------------------------------------------------------------
// LayerNorm: one warp per 192-wide row, bf16 output
// ---------------------------------------------------------------------------
__global__ __launch_bounds__(256) void ln_kernel(
    const float* __restrict__ x, const float* __restrict__ g,
    const float* __restrict__ b, __nv_bfloat16* __restrict__ out)
{
    int row  = blockIdx.x * 8 + (threadIdx.x >> 5);
    int lane = threadIdx.x & 31;
    const float* xp = x + (size_t)row * 192;
    float v[6]; float s = 0.f;
#pragma unroll
    for (int i = 0; i < 6; i++) { v[i] = xp[lane + 32*i]; s += v[i]; }
#pragma unroll
    for (int o = 16; o > 0; o >>= 1) s += __shfl_xor_sync(0xffffffffu, s, o);
    float mu = s * (1.f/192.f);
    float var = 0.f;
#pragma unroll
    for (int i = 0; i < 6; i++) { float d = v[i] - mu; var += d*d; }
#pragma unroll
    for (int o = 16; o > 0; o >>= 1) var += __shfl_xor_sync(0xffffffffu, var, o);
    float inv = rsqrtf(var * (1.f/192.f) + 1e-5f);
    __nv_bfloat16* op = out + (size_t)row * 192;
#pragma unroll
    for (int i = 0; i < 6; i++) {
        int c = lane + 32*i;
        op[c] = __float2bfloat16((v[i] - mu) * inv * g[c] + b[c]);
    }
}

// ---------------------------------------------------------------------------
// bf16 tensor-core GEMM, 3-stage cp.async pipeline + ldmatrix.
//   C[m,n] = act( A[m,:] @ W[:,n] + bias[n] ) (+ res[m,n])
// BM=256, BN=64, BK=32; 256 threads = 8 warps (4m x 2n), warp tile 64x32.
// Per k16 per warp: 6 ldmatrix feed 16 MMAs (2x density vs 32x32 tile).
// Dynamic smem: 3 stages x (256*SA + 32*SB) bf16 = 75264 B.
// M % 256 == 0, K % 32 == 0, N % 8 == 0 (BN-partial blocks allowed).
// ---------------------------------------------------------------------------
__device__ __forceinline__ void cp16(uint32_t dst, const void* src, bool ok) {
    int sz = ok ? 16 : 0;
    asm volatile("cp.async.cg.shared.global [%0], [%1], 16, %2;\n"
                 :: "r"(dst), "l"(src), "r"(sz));
}
__device__ __forceinline__ void ldmx4(unsigned r[4], uint32_t addr) {
    asm volatile("ldmatrix.sync.aligned.m8n8.x4.shared.b16 {%0,%1,%2,%3}, [%4];"
                 : "=r"(r[0]), "=r"(r[1]), "=r"(r[2]), "=r"(r[3]) : "r"(addr));
}
__device__ __forceinline__ void ldmx4t(unsigned r[4], uint32_t addr) {
    asm volatile("ldmatrix.sync.aligned.m8n8.x4.trans.shared.b16 {%0,%1,%2,%3}, [%4];"
                 : "=r"(r[0]), "=r"(r[1]), "=r"(r[2]), "=r"(r[3]) : "r"(addr));
}
__device__ __forceinline__ void mma_bf16(float c[4], const unsigned a[4],
                                         unsigned b0, unsigned b1) {
    asm volatile(
        "mma.sync.aligned.m16n8k16.row.col.f32.bf16.bf16.f32 "
        "{%0,%1,%2,%3}, {%4,%5,%6,%7}, {%8,%9}, {%0,%1,%2,%3};"
        : "+f"(c[0]), "+f"(c[1]), "+f"(c[2]), "+f"(c[3])
        : "r"(a[0]), "r"(a[1]), "r"(a[2]), "r"(a[3]), "r"(b0), "r"(b1));
}

#define SA 40
#define SB 72
#define GEMM_SMEM ((3 * (256 * SA + 32 * SB)) * 2)

__global__ __launch_bounds__(256) void gemm_bf16_kernel(
    const __nv_bfloat16* __restrict__ A, int lda,
    const __nv_bfloat16* __restrict__ W, int ldw,
    const float* __restrict__ bias,
    void* __restrict__ Cc, int ldc,
    int N, int K,
    const float* __restrict__ res, int act, int out_bf16)
{
    extern __shared__ __align__(16) __nv_bfloat16 smem[];
    __nv_bfloat16* Asm = smem;                    // 3 x 256*SA
    __nv_bfloat16* Bsm = smem + 3 * 256 * SA;     // 3 x 32*SB
    int tid  = threadIdx.x;
    int lane = tid & 31;
    int warp = tid >> 5;
    int m0 = blockIdx.y * 256;
    int n0 = blockIdx.x * 64;
    int wm0 = (warp >> 1) * 64;
    int wn0 = (warp & 1) * 32;
    int g  = lane >> 2, cq = lane & 3;
    int ln15 = lane & 15, hi8 = (lane >> 4) << 3;

    uint32_t sAb[3], sBb[3];
#pragma unroll
    for (int s = 0; s < 3; s++) {
        sAb[s] = (uint32_t)__cvta_generic_to_shared(Asm + s * 256 * SA);
        sBb[s] = (uint32_t)__cvta_generic_to_shared(Bsm + s * 32 * SB);
    }

    float acc[4][4][4];
#pragma unroll
    for (int mt = 0; mt < 4; mt++)
#pragma unroll
        for (int nt = 0; nt < 4; nt++)
#pragma unroll
            for (int r = 0; r < 4; r++) acc[mt][nt][r] = 0.f;

    // Loader lane assignments: A 256x32 (4 cp16/thread), B 32x64 (1 cp16)
    int a_r0 = tid >> 2, a_c = (tid & 3) << 3;
    int b_kr = tid >> 3, b_nq = (tid & 7) << 3;
    bool b_ok = (n0 + b_nq + 8) <= N;

    int T = K >> 5;
#define LOAD_TILE(slot, t_)                                                    \
    do {                                                                       \
        int kt_ = (t_) << 5;                                                   \
        _Pragma("unroll")                                                      \
        for (int i_ = 0; i_ < 4; i_++)                                         \
            cp16(sAb[slot] + ((a_r0 + i_ * 64) * SA + a_c) * 2,                \
                 A + (size_t)(m0 + a_r0 + i_ * 64) * lda + kt_ + a_c, true);   \
        cp16(sBb[slot] + (b_kr * SB + b_nq) * 2,                               \
             b_ok ? (const void*)(W + (size_t)(kt_ + b_kr) * ldw + n0 + b_nq)  \
                  : (const void*)W, b_ok);                                     \
        asm volatile("cp.async.commit_group;\n");                              \
    } while (0)

    LOAD_TILE(0, 0);
    if (T > 1) LOAD_TILE(1, 1);
    else asm volatile("cp.async.commit_group;\n");

    for (int t = 0; t < T; t++) {
        if (t + 2 < T) { int slot = (t + 2) % 3; LOAD_TILE(slot, t + 2); }
        if (t + 2 < T)      asm volatile("cp.async.wait_group 2;\n");
        else if (t + 1 < T) asm volatile("cp.async.wait_group 1;\n");
        else                asm volatile("cp.async.wait_group 0;\n");
        __syncthreads();

        uint32_t ab = sAb[t % 3], bb = sBb[t % 3];
#pragma unroll
        for (int kb = 0; kb < 32; kb += 16) {
            unsigned af[4][4], bf[2][4];
#pragma unroll
            for (int mt = 0; mt < 4; mt++)
                ldmx4(af[mt], ab + ((wm0 + mt*16 + ln15) * SA + kb + hi8) * 2);
#pragma unroll
            for (int np = 0; np < 2; np++)
                ldmx4t(bf[np], bb + ((kb + ln15) * SB + wn0 + np*16 + hi8) * 2);
#pragma unroll
            for (int mt = 0; mt < 4; mt++)
#pragma unroll
                for (int nt = 0; nt < 4; nt++)
                    mma_bf16(acc[mt][nt], af[mt],
                             bf[nt >> 1][(nt & 1) * 2],
                             bf[nt >> 1][(nt & 1) * 2 + 1]);
        }
        __syncthreads();
    }
#undef LOAD_TILE

    // -------- epilogue: bias (+gelu) (+residual), fp32 or bf16 out --------
#pragma unroll
    for (int mt = 0; mt < 4; mt++) {
        int row0 = m0 + wm0 + mt * 16 + g;
#pragma unroll
        for (int nt = 0; nt < 4; nt++) {
            int col = n0 + wn0 + nt * 8 + cq * 2;
            if (col < N) {
                float b0 = bias[col], b1 = bias[col + 1];
#pragma unroll
                for (int hh = 0; hh < 2; hh++) {
                    int row = row0 + 8 * hh;
                    float v0 = acc[mt][nt][hh * 2 + 0] + b0;
                    float v1 = acc[mt][nt][hh * 2 + 1] + b1;
                    if (act) { v0 = gelu_f(v0); v1 = gelu_f(v1); }
                    if (res) {
                        float2 rr = *(const float2*)&res[(size_t)row * ldc + col];
                        v0 += rr.x; v1 += rr.y;
                    }
                    if (out_bf16) {
                        *(__nv_bfloat162*)&((__nv_bfloat16*)Cc)[(size_t)row * ldc + col] =
                            __float22bfloat162_rn(make_float2(v0, v1));
                    } else {
                        *(float2*)&((float*)Cc)[(size_t)row * ldc + col] =
                            make_float2(v0, v1);
                    }
                }
            }
        }
    }
}

// ---------------------------------------------------------------------------
// Windowed PSA attention.  One block per 8x8 window (2048 windows).
// 384 threads = 64 q-tokens x 6 heads; softmax over 16 kv in registers.
// qkv is bf16 (stride 288: 192 q | 96 kv); fp32 math; bf16 output.
// ---------------------------------------------------------------------------
__global__ __launch_bounds__(384) void attn_kernel(
    const __nv_bfloat16* __restrict__ qkv,
    const float* __restrict__ bias_table,
    __nv_bfloat16* __restrict__ aw)
{
    __shared__ float ks[16][192];
    __shared__ float vs[16][192];
    __shared__ float bt[296];
    int w  = blockIdx.x;
    int b  = w >> 10;
    int wi = w & 1023;
    int wy = wi >> 5, wx = wi & 31;
    int gbase = b*65536 + wy*2048 + wx*8;
    int tid = threadIdx.x;

    for (int i = tid; i < 294; i += 384) bt[i] = bias_table[i];
    for (int i = tid; i < 3072; i += 384) {
        int kt = i / 192, f = i - kt*192;
        int p0 = kt >> 2, p1 = kt & 3;
        int s0 = f / 96;
        int s1 = (f / 48) & 1;
        int c  = f % 48;
        int g  = gbase + (p0*2 + s0)*256 + (p1*2 + s1);
        const __nv_bfloat16* row = qkv + (size_t)g*QKVLD + 192;
        ks[kt][f] = __bfloat162float(row[c]);
        vs[kt][f] = __bfloat162float(row[48 + c]);
    }
    __syncthreads();

    int h  = tid / 64;
    int qt = tid - h*64;
    int qi = qt >> 3, qj = qt & 7;
    int g  = gbase + qi*256 + qj;
    const __nv_bfloat16* qp = qkv + (size_t)g*QKVLD + h*32;
    float q[32];
#pragma unroll
    for (int d = 0; d < 32; d += 8) {
        uint4 raw = *(const uint4*)(qp + d);
        const __nv_bfloat162* p2 = (const __nv_bfloat162*)&raw;
#pragma unroll
        for (int j = 0; j < 4; j++) {
            float2 f2 = __bfloat1622float2(p2[j]);
            q[d + 2*j]     = f2.x * ATT_SCALE;
            q[d + 2*j + 1] = f2.y * ATT_SCALE;
        }
    }
    float sc[16]; float mx = -1e30f;
    int rq0 = (qi >> 1) + 3, rq1 = (qj >> 1) + 3;
#pragma unroll
    for (int kt = 0; kt < 16; kt++) {
        const float* kr = &ks[kt][h*32];
        float s = 0.f;
#pragma unroll
        for (int d = 0; d < 32; d++) s += q[d]*kr[d];
        int rel = (rq0 - (kt >> 2))*7 + rq1 - (kt & 3);
        s += bt[rel*6 + h];
        sc[kt] = s;
        mx = fmaxf(mx, s);
    }
    float sum = 0.f;
#pragma unroll
    for (int kt = 0; kt < 16; kt++) { sc[kt] = __expf(sc[kt] - mx); sum += sc[kt]; }
    float inv = 1.f / sum;
    float o[32];
#pragma unroll
    for (int d = 0; d < 32; d++) o[d] = 0.f;
#pragma unroll
    for (int kt = 0; kt < 16; kt++) {
        float a = sc[kt]*inv;
        const float* vr = &vs[kt][h*32];
#pragma unroll
        for (int d = 0; d < 32; d++) o[d] += a*vr[d];
    }
    __nv_bfloat162* op = (__nv_bfloat162*)(aw + (size_t)g*192 + h*32);
#pragma unroll
    for (int d = 0; d < 32; d += 2)
        op[d >> 1] = __float22bfloat162_rn(make_float2(o[d], o[d+1]));
}

// ---------------------------------------------------------------------------
// Depthwise 5x5 conv (channel-last, bf16 in/out) + GELU + residual:
//   out = h1 + gelu(conv(h1) + dwb)
// Block: 8 consecutive x-tokens (never straddles a row) x 128 channels.
// Neighborhood 5y x 12x x 128ch staged in smem (15 KB) — one global read
// per element instead of up to 25.
// ---------------------------------------------------------------------------
__global__ __launch_bounds__(256) void dwconv_kernel(
    const __nv_bfloat16* __restrict__ h1, const float* __restrict__ wk,
    const float* __restrict__ wb, __nv_bfloat16* __restrict__ out)
{
    __shared__ float ws[25][128];
    __shared__ float bs[128];
    __shared__ __align__(16) __nv_bfloat16 tile[5][12 * 128];
    int cb  = blockIdx.y * 128;
    int tid = threadIdx.x;
    for (int i = tid; i < 3200; i += 256) {
        int k = i >> 7, c = i & 127;
        ws[k][c] = wk[(size_t)(cb + c)*25 + k];
    }
    if (tid < 128) bs[tid] = wb[cb + tid];

    int token0 = blockIdx.x * 8;
    int b  = token0 >> 16;
    int p  = token0 & 65535;
    int y  = p >> 8, xb = p & 255;

    // Stage neighborhood: 5 x 12 x 32 uint2 (4 channels each) = 1920 loads
    for (int idx = tid; idx < 1920; idx += 256) {
        int dy = idx / 384;
        int r  = idx - dy * 384;
        int xx = r >> 5;
        int cg = r & 31;
        int gy = y + dy - 2;
        int gx = xb + xx - 2;
        uint2 v = make_uint2(0u, 0u);
        if ((unsigned)gy < 256u && (unsigned)gx < 256u)
            v = *(const uint2*)&h1[((size_t)(b*65536 + gy*256 + gx))*HID + cb + cg*4];
        *(uint2*)&tile[dy][xx*128 + cg*4] = v;
    }
    __syncthreads();

    int tl = tid >> 5;           // token within the 8-run (x offset)
    int cg = tid & 31;
    int token = token0 + tl;
    int ch = cb + cg*4;
    float4 acc    = make_float4(0.f, 0.f, 0.f, 0.f);
    float4 center = make_float4(0.f, 0.f, 0.f, 0.f);
#pragma unroll
    for (int dy = 0; dy < 5; dy++) {
#pragma unroll
        for (int dx = 0; dx < 5; dx++) {
            uint2 raw = *(const uint2*)&tile[dy][(tl + dx)*128 + cg*4];
            float2 f0 = __bfloat1622float2(*reinterpret_cast<__nv_bfloat162*>(&raw.x));
            float2 f1 = __bfloat1622float2(*reinterpret_cast<__nv_bfloat162*>(&raw.y));
            float4 v = make_float4(f0.x, f0.y, f1.x, f1.y);
            if (dy == 2 && dx == 2) center = v;
            float4 wv = *(const float4*)&ws[dy*5 + dx][cg*4];
            acc.x += v.x*wv.x; acc.y += v.y*wv.y;
            acc.z += v.z*wv.z; acc.w += v.w*wv.w;
        }
    }
    float4 bb = *(const float4*)&bs[cg*4];
    float2 r0, r1;
    r0.x = center.x + gelu_f(acc.x + bb.x);
    r0.y = center.y + gelu_f(acc.y + bb.y);
    r1.x = center.z + gelu_f(acc.z + bb.z);
    r1.y = center.w + gelu_f(acc.w + bb.w);
    uint2 o;
    *reinterpret_cast<__nv_bfloat162*>(&o.x) = __float22bfloat162_rn(r0);
    *reinterpret_cast<__nv_bfloat162*>(&o.y) = __float22bfloat162_rn(r1);
    *(uint2*)&out[(size_t)token*HID + ch] = o;
}

// ---------------------------------------------------------------------------
// Launch sequence (graph-capturable: kernel launches only)
// ---------------------------------------------------------------------------
extern "C" void kernel_launch(void* const* d_in, const int* in_sizes, int n_in,
                              void* d_out, int out_size)
{
    const float* x    = (const float*)d_in[0];
    const float* g1   = (const float*)d_in[1];
    const float* be1  = (const float*)d_in[2];
    const float* wq   = (const float*)d_in[3];
    const float* bq   = (const float*)d_in[4];
    const float* wkv  = (const float*)d_in[5];
    const float* bkv  = (const float*)d_in[6];
    const float* btab = (const float*)d_in[7];
    const float* wproj= (const float*)d_in[8];
    const float* bproj= (const float*)d_in[9];
    const float* g2   = (const float*)d_in[10];
    const float* be2  = (const float*)d_in[11];
    const float* w1f  = (const float*)d_in[12];
    const float* b1f  = (const float*)d_in[13];
    const float* dwk  = (const float*)d_in[14];
    const float* dwb  = (const float*)d_in[15];
    const float* w2f  = (const float*)d_in[16];
    const float* b2f  = (const float*)d_in[17];
    float* out = (float*)d_out;

    __nv_bfloat16 *xn, *qkvb, *aw, *h1, *h, *wb;
    float *x2, *bqkv;
    cudaGetSymbolAddress((void**)&xn,   g_xn);
    cudaGetSymbolAddress((void**)&qkvb, g_qkvb);
    cudaGetSymbolAddress((void**)&aw,   g_aw);
    cudaGetSymbolAddress((void**)&x2,   g_x2);
    cudaGetSymbolAddress((void**)&h1,   g_h1);
    cudaGetSymbolAddress((void**)&h,    g_h);
    cudaGetSymbolAddress((void**)&wb,   g_wb);
    cudaGetSymbolAddress((void**)&bqkv, g_bqkv);

    cudaFuncSetAttribute(gemm_bf16_kernel,
                         cudaFuncAttributeMaxDynamicSharedMemorySize, GEMM_SMEM);

    // 0. Weight/bias prep (bf16, QKV concat)
    prep_kernel<<<(387072 + 255)/256, 256>>>(wq, wkv, wproj, w1f, w2f, wb);
    biasprep_kernel<<<1, 288>>>(bq, bkv, bqkv);

    // 1. LN1 -> xn (bf16)
    ln_kernel<<<NTOK/8, 256>>>(x, g1, be1, xn);
    // 2. QKV = xn @ wqkv + bqkv  (bf16, ldc=288; N=288 -> 5 n-blocks)
    gemm_bf16_kernel<<<dim3(5, NTOK/256), 256, GEMM_SMEM>>>(
        xn, 192, wb + WB_WQKV, 288, bqkv, qkvb, QKVLD, 288, 192, nullptr, 0, 1);
    // 3. Window attention -> aw (bf16, token order)
    attn_kernel<<<2048, 384>>>(qkvb, btab, aw);
    // 4. x2 = aw @ wproj + bproj + x  (fp32)
    gemm_bf16_kernel<<<dim3(3, NTOK/256), 256, GEMM_SMEM>>>(
        aw, 192, wb + WB_WPROJ, 192, bproj, x2, 192, 192, 192, x, 0, 0);
    // 5. LN2 -> xn (bf16)
    ln_kernel<<<NTOK/8, 256>>>(x2, g2, be2, xn);
    // 6. h1 = gelu(xn @ w1f + b1f)  (bf16)
    gemm_bf16_kernel<<<dim3(12, NTOK/256), 256, GEMM_SMEM>>>(
        xn, 192, wb + WB_W1F, HID, b1f, h1, HID, HID, 192, nullptr, 1, 1);
    // 7. h = h1 + gelu(dwconv(h1) + dwb)  (bf16)
    dwconv_kernel<<<dim3(NTOK/8, 6), 256>>>(h1, dwk, dwb, h);
    // 8. out = h @ w2f + b2f + x2  (fp32)
    gemm_bf16_kernel<<<dim3(3, NTOK/256), 256, GEMM_SMEM>>>(
        h, HID, wb + WB_W2F, 192, b2f, out, 192, 192, HID, x2, 0, 0);
}

// round 9
// speedup vs baseline: 1.0213x; 1.0213x over previous
#include <cuda_runtime.h>
#include <cuda_bf16.h>
#include <cstdint>
#include <math.h>

// ---------------------------------------------------------------------------
// Problem constants
//   B=2, H=W=256, C=192, HEADS=6, HEAD_DIM=32, WS=8, PW=4, HIDDEN=768
//   NTOK = B*H*W = 131072 tokens
// ---------------------------------------------------------------------------
#define NTOK   131072
#define QKVLD  288      // 192 (q) + 96 (kv) per token, bf16
#define HID    768
#define ATT_SCALE 0.17677669529663688f   // 32^-0.5

// Scratch (static device allocations — no cudaMalloc allowed)
__device__ __align__(16) __nv_bfloat16 g_xn  [(size_t)NTOK * 192]; // LN out
__device__ __align__(16) __nv_bfloat16 g_qkvb[(size_t)NTOK * QKVLD];
__device__ __align__(16) __nv_bfloat16 g_aw  [(size_t)NTOK * 192]; // attn out
__device__ __align__(16) float         g_x2  [(size_t)NTOK * 192]; // resid
__device__ __align__(16) __nv_bfloat16 g_h1  [(size_t)NTOK * HID]; // gelu(fc1)
__device__ __align__(16) __nv_bfloat16 g_h   [(size_t)NTOK * HID]; // ffn hidden
// bf16 weights: wqkv (192x288) | wproj | w1f | w2f
#define WB_WQKV  0
#define WB_WPROJ 55296
#define WB_W1F   92160
#define WB_W2F   239616
__device__ __align__(16) __nv_bfloat16 g_wb[387072];
__device__ __align__(16) float g_bqkv[288];

__device__ __forceinline__ float gelu_f(float v) {
    return 0.5f * v * (1.0f + erff(v * 0.70710678118654752440f));
}

// ---------------------------------------------------------------------------
// Weight/bias prep: concat wq|wkv into 192x288 + convert all weights to bf16
// ---------------------------------------------------------------------------
__global__ __launch_bounds__(256) void prep_kernel(
    const float* __restrict__ wq, const float* __restrict__ wkv,
    const float* __restrict__ wproj, const float* __restrict__ w1f,
    const float* __restrict__ w2f, __nv_bfloat16* __restrict__ wb,
    const float* __restrict__ bq, const float* __restrict__ bkv,
    float* __restrict__ bqkv)
{
    int i = blockIdx.x * 256 + threadIdx.x;
    if (i < 288) bqkv[i] = (i < 192) ? bq[i] : bkv[i - 192];
    if (i >= 387072) return;
    float v;
    if (i < 55296) {
        int row = i / 288, col = i - row * 288;
        v = (col < 192) ? wq[row * 192 + col] : wkv[row * 96 + col - 192];
    } else if (i < 92160) {
        v = wproj[i - 55296];
    } else if (i < 239616) {
        v = w1f[i - 92160];
    } else {
        v = w2f[i - 239616];
    }
    wb[i] = __float2bfloat16(v);
}

// ---------------------------------------------------------------------------
// LayerNorm: one warp per 192-wide row, bf16 output
// ---------------------------------------------------------------------------
__global__ __launch_bounds__(256) void ln_kernel(
    const float* __restrict__ x, const float* __restrict__ g,
    const float* __restrict__ b, __nv_bfloat16* __restrict__ out)
{
    int row  = blockIdx.x * 8 + (threadIdx.x >> 5);
    int lane = threadIdx.x & 31;
    const float* xp = x + (size_t)row * 192;
    float v[6]; float s = 0.f;
#pragma unroll
    for (int i = 0; i < 6; i++) { v[i] = xp[lane + 32*i]; s += v[i]; }
#pragma unroll
    for (int o = 16; o > 0; o >>= 1) s += __shfl_xor_sync(0xffffffffu, s, o);
    float mu = s * (1.f/192.f);
    float var = 0.f;
#pragma unroll
    for (int i = 0; i < 6; i++) { float d = v[i] - mu; var += d*d; }
#pragma unroll
    for (int o = 16; o > 0; o >>= 1) var += __shfl_xor_sync(0xffffffffu, var, o);
    float inv = rsqrtf(var * (1.f/192.f) + 1e-5f);
    __nv_bfloat16* op = out + (size_t)row * 192;
#pragma unroll
    for (int i = 0; i < 6; i++) {
        int c = lane + 32*i;
        op[c] = __float2bfloat16((v[i] - mu) * inv * g[c] + b[c]);
    }
}

// ---------------------------------------------------------------------------
// bf16 tensor-core GEMM, 3-stage cp.async pipeline + ldmatrix.
//   C[m,n] = act( A[m,:] @ W[:,n] + bias[n] ) (+ res[m,n])
// BM=128, BN=64, BK=32; 256 threads = 8 warps (4m x 2n), warp tile 32x32.
// (R6 configuration — proven fastest on this target.)
// ---------------------------------------------------------------------------
__device__ __forceinline__ void cp16(uint32_t dst, const void* src, bool ok) {
    int sz = ok ? 16 : 0;
    asm volatile("cp.async.cg.shared.global [%0], [%1], 16, %2;\n"
                 :: "r"(dst), "l"(src), "r"(sz));
}
__device__ __forceinline__ void ldmx4(unsigned r[4], uint32_t addr) {
    asm volatile("ldmatrix.sync.aligned.m8n8.x4.shared.b16 {%0,%1,%2,%3}, [%4];"
                 : "=r"(r[0]), "=r"(r[1]), "=r"(r[2]), "=r"(r[3]) : "r"(addr));
}
__device__ __forceinline__ void ldmx4t(unsigned r[4], uint32_t addr) {
    asm volatile("ldmatrix.sync.aligned.m8n8.x4.trans.shared.b16 {%0,%1,%2,%3}, [%4];"
                 : "=r"(r[0]), "=r"(r[1]), "=r"(r[2]), "=r"(r[3]) : "r"(addr));
}
__device__ __forceinline__ void mma_bf16(float c[4], const unsigned a[4],
                                         unsigned b0, unsigned b1) {
    asm volatile(
        "mma.sync.aligned.m16n8k16.row.col.f32.bf16.bf16.f32 "
        "{%0,%1,%2,%3}, {%4,%5,%6,%7}, {%8,%9}, {%0,%1,%2,%3};"
        : "+f"(c[0]), "+f"(c[1]), "+f"(c[2]), "+f"(c[3])
        : "r"(a[0]), "r"(a[1]), "r"(a[2]), "r"(a[3]), "r"(b0), "r"(b1));
}

#define SA 40
#define SB 72

__global__ __launch_bounds__(256) void gemm_bf16_kernel(
    const __nv_bfloat16* __restrict__ A, int lda,
    const __nv_bfloat16* __restrict__ W, int ldw,
    const float* __restrict__ bias,
    void* __restrict__ Cc, int ldc,
    int N, int K,
    const float* __restrict__ res, int act, int out_bf16)
{
    __shared__ __align__(16) __nv_bfloat16 As[3][128 * SA];
    __shared__ __align__(16) __nv_bfloat16 Bs[3][32 * SB];
    int tid  = threadIdx.x;
    int lane = tid & 31;
    int warp = tid >> 5;
    int m0 = blockIdx.y * 128;
    int n0 = blockIdx.x * 64;
    int wm0 = (warp >> 1) * 32;
    int wn0 = (warp & 1) * 32;
    int g  = lane >> 2, cq = lane & 3;
    int ln15 = lane & 15, hi8 = (lane >> 4) << 3;

    uint32_t sAb[3], sBb[3];
#pragma unroll
    for (int s = 0; s < 3; s++) {
        sAb[s] = (uint32_t)__cvta_generic_to_shared(&As[s][0]);
        sBb[s] = (uint32_t)__cvta_generic_to_shared(&Bs[s][0]);
    }

    float acc[2][4][4];
#pragma unroll
    for (int mt = 0; mt < 2; mt++)
#pragma unroll
        for (int nt = 0; nt < 4; nt++)
#pragma unroll
            for (int r = 0; r < 4; r++) acc[mt][nt][r] = 0.f;

    int a_r0 = tid >> 2, a_c = (tid & 3) << 3;
    int b_kr = tid >> 3, b_nq = (tid & 7) << 3;
    bool b_ok = (n0 + b_nq + 8) <= N;

    int T = K >> 5;
#define LOAD_TILE(slot, t_)                                                    \
    do {                                                                       \
        int kt_ = (t_) << 5;                                                   \
        cp16(sAb[slot] + (a_r0 * SA + a_c) * 2,                                \
             A + (size_t)(m0 + a_r0) * lda + kt_ + a_c, true);                 \
        cp16(sAb[slot] + ((a_r0 + 64) * SA + a_c) * 2,                         \
             A + (size_t)(m0 + a_r0 + 64) * lda + kt_ + a_c, true);            \
        cp16(sBb[slot] + (b_kr * SB + b_nq) * 2,                               \
             b_ok ? (const void*)(W + (size_t)(kt_ + b_kr) * ldw + n0 + b_nq)  \
                  : (const void*)W, b_ok);                                     \
        asm volatile("cp.async.commit_group;\n");                              \
    } while (0)

    LOAD_TILE(0, 0);
    if (T > 1) LOAD_TILE(1, 1);
    else asm volatile("cp.async.commit_group;\n");

    for (int t = 0; t < T; t++) {
        if (t + 2 < T) { int slot = (t + 2) % 3; LOAD_TILE(slot, t + 2); }
        if (t + 2 < T)      asm volatile("cp.async.wait_group 2;\n");
        else if (t + 1 < T) asm volatile("cp.async.wait_group 1;\n");
        else                asm volatile("cp.async.wait_group 0;\n");
        __syncthreads();

        uint32_t ab = sAb[t % 3], bb = sBb[t % 3];
#pragma unroll
        for (int kb = 0; kb < 32; kb += 16) {
            unsigned af[2][4], bf[2][4];
#pragma unroll
            for (int mt = 0; mt < 2; mt++)
                ldmx4(af[mt], ab + ((wm0 + mt*16 + ln15) * SA + kb + hi8) * 2);
#pragma unroll
            for (int np = 0; np < 2; np++)
                ldmx4t(bf[np], bb + ((kb + ln15) * SB + wn0 + np*16 + hi8) * 2);
#pragma unroll
            for (int mt = 0; mt < 2; mt++)
#pragma unroll
                for (int nt = 0; nt < 4; nt++)
                    mma_bf16(acc[mt][nt], af[mt],
                             bf[nt >> 1][(nt & 1) * 2],
                             bf[nt >> 1][(nt & 1) * 2 + 1]);
        }
        __syncthreads();
    }
#undef LOAD_TILE

    // -------- epilogue: bias (+gelu) (+residual), fp32 or bf16 out --------
#pragma unroll
    for (int mt = 0; mt < 2; mt++) {
        int row0 = m0 + wm0 + mt * 16 + g;
#pragma unroll
        for (int nt = 0; nt < 4; nt++) {
            int col = n0 + wn0 + nt * 8 + cq * 2;
            if (col < N) {
                float b0 = bias[col], b1 = bias[col + 1];
#pragma unroll
                for (int hh = 0; hh < 2; hh++) {
                    int row = row0 + 8 * hh;
                    float v0 = acc[mt][nt][hh * 2 + 0] + b0;
                    float v1 = acc[mt][nt][hh * 2 + 1] + b1;
                    if (act) { v0 = gelu_f(v0); v1 = gelu_f(v1); }
                    if (res) {
                        float2 rr = *(const float2*)&res[(size_t)row * ldc + col];
                        v0 += rr.x; v1 += rr.y;
                    }
                    if (out_bf16) {
                        *(__nv_bfloat162*)&((__nv_bfloat16*)Cc)[(size_t)row * ldc + col] =
                            __float22bfloat162_rn(make_float2(v0, v1));
                    } else {
                        *(float2*)&((float*)Cc)[(size_t)row * ldc + col] =
                            make_float2(v0, v1);
                    }
                }
            }
        }
    }
}

// ---------------------------------------------------------------------------
// Windowed PSA attention.  One block per 8x8 window (2048 windows).
// 384 threads = 64 q-tokens x 6 heads; softmax over 16 kv in registers.
// ---------------------------------------------------------------------------
__global__ __launch_bounds__(384) void attn_kernel(
    const __nv_bfloat16* __restrict__ qkv,
    const float* __restrict__ bias_table,
    __nv_bfloat16* __restrict__ aw)
{
    __shared__ float ks[16][192];
    __shared__ float vs[16][192];
    __shared__ float bt[296];
    int w  = blockIdx.x;
    int b  = w >> 10;
    int wi = w & 1023;
    int wy = wi >> 5, wx = wi & 31;
    int gbase = b*65536 + wy*2048 + wx*8;
    int tid = threadIdx.x;

    for (int i = tid; i < 294; i += 384) bt[i] = bias_table[i];
    for (int i = tid; i < 3072; i += 384) {
        int kt = i / 192, f = i - kt*192;
        int p0 = kt >> 2, p1 = kt & 3;
        int s0 = f / 96;
        int s1 = (f / 48) & 1;
        int c  = f % 48;
        int g  = gbase + (p0*2 + s0)*256 + (p1*2 + s1);
        const __nv_bfloat16* row = qkv + (size_t)g*QKVLD + 192;
        ks[kt][f] = __bfloat162float(row[c]);
        vs[kt][f] = __bfloat162float(row[48 + c]);
    }
    __syncthreads();

    int h  = tid / 64;
    int qt = tid - h*64;
    int qi = qt >> 3, qj = qt & 7;
    int g  = gbase + qi*256 + qj;
    const __nv_bfloat16* qp = qkv + (size_t)g*QKVLD + h*32;
    float q[32];
#pragma unroll
    for (int d = 0; d < 32; d += 8) {
        uint4 raw = *(const uint4*)(qp + d);
        const __nv_bfloat162* p2 = (const __nv_bfloat162*)&raw;
#pragma unroll
        for (int j = 0; j < 4; j++) {
            float2 f2 = __bfloat1622float2(p2[j]);
            q[d + 2*j]     = f2.x * ATT_SCALE;
            q[d + 2*j + 1] = f2.y * ATT_SCALE;
        }
    }
    float sc[16]; float mx = -1e30f;
    int rq0 = (qi >> 1) + 3, rq1 = (qj >> 1) + 3;
#pragma unroll
    for (int kt = 0; kt < 16; kt++) {
        const float* kr = &ks[kt][h*32];
        float s = 0.f;
#pragma unroll
        for (int d = 0; d < 32; d++) s += q[d]*kr[d];
        int rel = (rq0 - (kt >> 2))*7 + rq1 - (kt & 3);
        s += bt[rel*6 + h];
        sc[kt] = s;
        mx = fmaxf(mx, s);
    }
    float sum = 0.f;
#pragma unroll
    for (int kt = 0; kt < 16; kt++) { sc[kt] = __expf(sc[kt] - mx); sum += sc[kt]; }
    float inv = 1.f / sum;
    float o[32];
#pragma unroll
    for (int d = 0; d < 32; d++) o[d] = 0.f;
#pragma unroll
    for (int kt = 0; kt < 16; kt++) {
        float a = sc[kt]*inv;
        const float* vr = &vs[kt][h*32];
#pragma unroll
        for (int d = 0; d < 32; d++) o[d] += a*vr[d];
    }
    __nv_bfloat162* op = (__nv_bfloat162*)(aw + (size_t)g*192 + h*32);
#pragma unroll
    for (int d = 0; d < 32; d += 2)
        op[d >> 1] = __float22bfloat162_rn(make_float2(o[d], o[d+1]));
}

// ---------------------------------------------------------------------------
// Depthwise 5x5 conv (channel-last, bf16 in/out) + GELU + residual:
//   out = h1 + gelu(conv(h1) + dwb)
// Block: 8 consecutive x-tokens (never straddles a row) x 128 channels.
// Neighborhood 5y x 12x x 128ch staged in smem (15 KB) — one global read
// per element instead of ~3.3x redundant L1 traffic.
// ---------------------------------------------------------------------------
__global__ __launch_bounds__(256) void dwconv_kernel(
    const __nv_bfloat16* __restrict__ h1, const float* __restrict__ wk,
    const float* __restrict__ wb, __nv_bfloat16* __restrict__ out)
{
    __shared__ float ws[25][128];
    __shared__ float bs[128];
    __shared__ __align__(16) __nv_bfloat16 tile[5][12 * 128];
    int cb  = blockIdx.y * 128;
    int tid = threadIdx.x;
    for (int i = tid; i < 3200; i += 256) {
        int k = i >> 7, c = i & 127;
        ws[k][c] = wk[(size_t)(cb + c)*25 + k];
    }
    if (tid < 128) bs[tid] = wb[cb + tid];

    int token0 = blockIdx.x * 8;
    int b  = token0 >> 16;
    int p  = token0 & 65535;
    int y  = p >> 8, xb = p & 255;

    // Stage neighborhood: 5 x 12 x 32 uint2 (4 channels each) = 1920 loads
    for (int idx = tid; idx < 1920; idx += 256) {
        int dy = idx / 384;
        int r  = idx - dy * 384;
        int xx = r >> 5;
        int cg = r & 31;
        int gy = y + dy - 2;
        int gx = xb + xx - 2;
        uint2 v = make_uint2(0u, 0u);
        if ((unsigned)gy < 256u && (unsigned)gx < 256u)
            v = *(const uint2*)&h1[((size_t)(b*65536 + gy*256 + gx))*HID + cb + cg*4];
        *(uint2*)&tile[dy][xx*128 + cg*4] = v;
    }
    __syncthreads();

    int tl = tid >> 5;           // token within the 8-run (x offset)
    int cg = tid & 31;
    int token = token0 + tl;
    int ch = cb + cg*4;
    float4 acc    = make_float4(0.f, 0.f, 0.f, 0.f);
    float4 center = make_float4(0.f, 0.f, 0.f, 0.f);
#pragma unroll
    for (int dy = 0; dy < 5; dy++) {
#pragma unroll
        for (int dx = 0; dx < 5; dx++) {
            uint2 raw = *(const uint2*)&tile[dy][(tl + dx)*128 + cg*4];
            float2 f0 = __bfloat1622float2(*reinterpret_cast<__nv_bfloat162*>(&raw.x));
            float2 f1 = __bfloat1622float2(*reinterpret_cast<__nv_bfloat162*>(&raw.y));
            float4 v = make_float4(f0.x, f0.y, f1.x, f1.y);
            if (dy == 2 && dx == 2) center = v;
            float4 wv = *(const float4*)&ws[dy*5 + dx][cg*4];
            acc.x += v.x*wv.x; acc.y += v.y*wv.y;
            acc.z += v.z*wv.z; acc.w += v.w*wv.w;
        }
    }
    float4 bb = *(const float4*)&bs[cg*4];
    float2 r0, r1;
    r0.x = center.x + gelu_f(acc.x + bb.x);
    r0.y = center.y + gelu_f(acc.y + bb.y);
    r1.x = center.z + gelu_f(acc.z + bb.z);
    r1.y = center.w + gelu_f(acc.w + bb.w);
    uint2 o;
    *reinterpret_cast<__nv_bfloat162*>(&o.x) = __float22bfloat162_rn(r0);
    *reinterpret_cast<__nv_bfloat162*>(&o.y) = __float22bfloat162_rn(r1);
    *(uint2*)&out[(size_t)token*HID + ch] = o;
}

// ---------------------------------------------------------------------------
// Launch sequence (graph-capturable: kernel launches only)
// ---------------------------------------------------------------------------
extern "C" void kernel_launch(void* const* d_in, const int* in_sizes, int n_in,
                              void* d_out, int out_size)
{
    const float* x    = (const float*)d_in[0];
    const float* g1   = (const float*)d_in[1];
    const float* be1  = (const float*)d_in[2];
    const float* wq   = (const float*)d_in[3];
    const float* bq   = (const float*)d_in[4];
    const float* wkv  = (const float*)d_in[5];
    const float* bkv  = (const float*)d_in[6];
    const float* btab = (const float*)d_in[7];
    const float* wproj= (const float*)d_in[8];
    const float* bproj= (const float*)d_in[9];
    const float* g2   = (const float*)d_in[10];
    const float* be2  = (const float*)d_in[11];
    const float* w1f  = (const float*)d_in[12];
    const float* b1f  = (const float*)d_in[13];
    const float* dwk  = (const float*)d_in[14];
    const float* dwb  = (const float*)d_in[15];
    const float* w2f  = (const float*)d_in[16];
    const float* b2f  = (const float*)d_in[17];
    float* out = (float*)d_out;

    __nv_bfloat16 *xn, *qkvb, *aw, *h1, *h, *wb;
    float *x2, *bqkv;
    cudaGetSymbolAddress((void**)&xn,   g_xn);
    cudaGetSymbolAddress((void**)&qkvb, g_qkvb);
    cudaGetSymbolAddress((void**)&aw,   g_aw);
    cudaGetSymbolAddress((void**)&x2,   g_x2);
    cudaGetSymbolAddress((void**)&h1,   g_h1);
    cudaGetSymbolAddress((void**)&h,    g_h);
    cudaGetSymbolAddress((void**)&wb,   g_wb);
    cudaGetSymbolAddress((void**)&bqkv, g_bqkv);

    // 0. Weight/bias prep (bf16, QKV concat)
    prep_kernel<<<(387072 + 255)/256, 256>>>(wq, wkv, wproj, w1f, w2f, wb,
                                             bq, bkv, bqkv);

    // 1. LN1 -> xn (bf16)
    ln_kernel<<<NTOK/8, 256>>>(x, g1, be1, xn);
    // 2. QKV = xn @ wqkv + bqkv  (bf16, ldc=288; N=288 -> 5 n-blocks)
    gemm_bf16_kernel<<<dim3(5, NTOK/128), 256>>>(xn, 192, wb + WB_WQKV, 288, bqkv,
                                                 qkvb, QKVLD, 288, 192,
                                                 nullptr, 0, 1);
    // 3. Window attention -> aw (bf16, token order)
    attn_kernel<<<2048, 384>>>(qkvb, btab, aw);
    // 4. x2 = aw @ wproj + bproj + x  (fp32)
    gemm_bf16_kernel<<<dim3(3, NTOK/128), 256>>>(aw, 192, wb + WB_WPROJ, 192, bproj,
                                                 x2, 192, 192, 192,
                                                 x, 0, 0);
    // 5. LN2 -> xn (bf16)
    ln_kernel<<<NTOK/8, 256>>>(x2, g2, be2, xn);
    // 6. h1 = gelu(xn @ w1f + b1f)  (bf16)
    gemm_bf16_kernel<<<dim3(12, NTOK/128), 256>>>(xn, 192, wb + WB_W1F, HID, b1f,
                                                  h1, HID, HID, 192,
                                                  nullptr, 1, 1);
    // 7. h = h1 + gelu(dwconv(h1) + dwb)  (bf16, smem-tiled)
    dwconv_kernel<<<dim3(NTOK/8, 6), 256>>>(h1, dwk, dwb, h);
    // 8. out = h @ w2f + b2f + x2  (fp32)
    gemm_bf16_kernel<<<dim3(3, NTOK/128), 256>>>(h, HID, wb + WB_W2F, 192, b2f,
                                                 out, 192, 192, HID,
                                                 x2, 0, 0);
}

// round 10
// speedup vs baseline: 1.3645x; 1.3360x over previous
#include <cuda_runtime.h>
#include <cuda_bf16.h>
#include <cstdint>
#include <math.h>

// ---------------------------------------------------------------------------
// Problem constants
//   B=2, H=W=256, C=192, HEADS=6, HEAD_DIM=32, WS=8, PW=4, HIDDEN=768
//   NTOK = B*H*W = 131072 tokens
// ---------------------------------------------------------------------------
#define NTOK   131072
#define QKVLD  288      // 192 (q) + 96 (kv) per token, bf16
#define HID    768
#define ATT_SCALE 0.17677669529663688f   // 32^-0.5

// Scratch (static device allocations — no cudaMalloc allowed)
__device__ __align__(16) __nv_bfloat16 g_xn  [(size_t)NTOK * 192]; // LN out
__device__ __align__(16) __nv_bfloat16 g_qkvb[(size_t)NTOK * QKVLD];
__device__ __align__(16) __nv_bfloat16 g_aw  [(size_t)NTOK * 192]; // attn out
__device__ __align__(16) float         g_x2  [(size_t)NTOK * 192]; // resid
__device__ __align__(16) __nv_bfloat16 g_h1  [(size_t)NTOK * HID]; // gelu(fc1)
__device__ __align__(16) __nv_bfloat16 g_h   [(size_t)NTOK * HID]; // ffn hidden
// bf16 weights: wqkv (192x288) | wproj | w1f | w2f
#define WB_WQKV  0
#define WB_WPROJ 55296
#define WB_W1F   92160
#define WB_W2F   239616
__device__ __align__(16) __nv_bfloat16 g_wb[387072];
__device__ __align__(16) float g_bqkv[288];

__device__ __forceinline__ float gelu_f(float v) {
    return 0.5f * v * (1.0f + erff(v * 0.70710678118654752440f));
}

// ---------------------------------------------------------------------------
// Weight/bias prep: concat wq|wkv into 192x288 + convert all weights to bf16
// ---------------------------------------------------------------------------
__global__ __launch_bounds__(256) void prep_kernel(
    const float* __restrict__ wq, const float* __restrict__ wkv,
    const float* __restrict__ wproj, const float* __restrict__ w1f,
    const float* __restrict__ w2f, __nv_bfloat16* __restrict__ wb,
    const float* __restrict__ bq, const float* __restrict__ bkv,
    float* __restrict__ bqkv)
{
    int i = blockIdx.x * 256 + threadIdx.x;
    if (i < 288) bqkv[i] = (i < 192) ? bq[i] : bkv[i - 192];
    if (i >= 387072) return;
    float v;
    if (i < 55296) {
        int row = i / 288, col = i - row * 288;
        v = (col < 192) ? wq[row * 192 + col] : wkv[row * 96 + col - 192];
    } else if (i < 92160) {
        v = wproj[i - 55296];
    } else if (i < 239616) {
        v = w1f[i - 92160];
    } else {
        v = w2f[i - 239616];
    }
    wb[i] = __float2bfloat16(v);
}

// ---------------------------------------------------------------------------
// LayerNorm: one warp per 192-wide row, bf16 output
// ---------------------------------------------------------------------------
__global__ __launch_bounds__(256) void ln_kernel(
    const float* __restrict__ x, const float* __restrict__ g,
    const float* __restrict__ b, __nv_bfloat16* __restrict__ out)
{
    int row  = blockIdx.x * 8 + (threadIdx.x >> 5);
    int lane = threadIdx.x & 31;
    const float* xp = x + (size_t)row * 192;
    float v[6]; float s = 0.f;
#pragma unroll
    for (int i = 0; i < 6; i++) { v[i] = xp[lane + 32*i]; s += v[i]; }
#pragma unroll
    for (int o = 16; o > 0; o >>= 1) s += __shfl_xor_sync(0xffffffffu, s, o);
    float mu = s * (1.f/192.f);
    float var = 0.f;
#pragma unroll
    for (int i = 0; i < 6; i++) { float d = v[i] - mu; var += d*d; }
#pragma unroll
    for (int o = 16; o > 0; o >>= 1) var += __shfl_xor_sync(0xffffffffu, var, o);
    float inv = rsqrtf(var * (1.f/192.f) + 1e-5f);
    __nv_bfloat16* op = out + (size_t)row * 192;
#pragma unroll
    for (int i = 0; i < 6; i++) {
        int c = lane + 32*i;
        op[c] = __float2bfloat16((v[i] - mu) * inv * g[c] + b[c]);
    }
}

// ---------------------------------------------------------------------------
// bf16 tensor-core GEMM, 3-stage cp.async pipeline + ldmatrix.
//   C[m,n] = act( A[m,:] @ W[:,n] + bias[n] ) (+ res[m,n])
// BM=128, BN=64, BK=32; 256 threads = 8 warps (4m x 2n), warp tile 32x32.
// (R6 configuration — proven fastest on this target.)
// ---------------------------------------------------------------------------
__device__ __forceinline__ void cp16(uint32_t dst, const void* src, bool ok) {
    int sz = ok ? 16 : 0;
    asm volatile("cp.async.cg.shared.global [%0], [%1], 16, %2;\n"
                 :: "r"(dst), "l"(src), "r"(sz));
}
__device__ __forceinline__ void ldmx4(unsigned r[4], uint32_t addr) {
    asm volatile("ldmatrix.sync.aligned.m8n8.x4.shared.b16 {%0,%1,%2,%3}, [%4];"
                 : "=r"(r[0]), "=r"(r[1]), "=r"(r[2]), "=r"(r[3]) : "r"(addr));
}
__device__ __forceinline__ void ldmx4t(unsigned r[4], uint32_t addr) {
    asm volatile("ldmatrix.sync.aligned.m8n8.x4.trans.shared.b16 {%0,%1,%2,%3}, [%4];"
                 : "=r"(r[0]), "=r"(r[1]), "=r"(r[2]), "=r"(r[3]) : "r"(addr));
}
__device__ __forceinline__ void mma_bf16(float c[4], const unsigned a[4],
                                         unsigned b0, unsigned b1) {
    asm volatile(
        "mma.sync.aligned.m16n8k16.row.col.f32.bf16.bf16.f32 "
        "{%0,%1,%2,%3}, {%4,%5,%6,%7}, {%8,%9}, {%0,%1,%2,%3};"
        : "+f"(c[0]), "+f"(c[1]), "+f"(c[2]), "+f"(c[3])
        : "r"(a[0]), "r"(a[1]), "r"(a[2]), "r"(a[3]), "r"(b0), "r"(b1));
}

#define SA 40
#define SB 72

__global__ __launch_bounds__(256) void gemm_bf16_kernel(
    const __nv_bfloat16* __restrict__ A, int lda,
    const __nv_bfloat16* __restrict__ W, int ldw,
    const float* __restrict__ bias,
    void* __restrict__ Cc, int ldc,
    int N, int K,
    const float* __restrict__ res, int act, int out_bf16)
{
    __shared__ __align__(16) __nv_bfloat16 As[3][128 * SA];
    __shared__ __align__(16) __nv_bfloat16 Bs[3][32 * SB];
    int tid  = threadIdx.x;
    int lane = tid & 31;
    int warp = tid >> 5;
    int m0 = blockIdx.y * 128;
    int n0 = blockIdx.x * 64;
    int wm0 = (warp >> 1) * 32;
    int wn0 = (warp & 1) * 32;
    int g  = lane >> 2, cq = lane & 3;
    int ln15 = lane & 15, hi8 = (lane >> 4) << 3;

    uint32_t sAb[3], sBb[3];
#pragma unroll
    for (int s = 0; s < 3; s++) {
        sAb[s] = (uint32_t)__cvta_generic_to_shared(&As[s][0]);
        sBb[s] = (uint32_t)__cvta_generic_to_shared(&Bs[s][0]);
    }

    float acc[2][4][4];
#pragma unroll
    for (int mt = 0; mt < 2; mt++)
#pragma unroll
        for (int nt = 0; nt < 4; nt++)
#pragma unroll
            for (int r = 0; r < 4; r++) acc[mt][nt][r] = 0.f;

    int a_r0 = tid >> 2, a_c = (tid & 3) << 3;
    int b_kr = tid >> 3, b_nq = (tid & 7) << 3;
    bool b_ok = (n0 + b_nq + 8) <= N;

    int T = K >> 5;
#define LOAD_TILE(slot, t_)                                                    \
    do {                                                                       \
        int kt_ = (t_) << 5;                                                   \
        cp16(sAb[slot] + (a_r0 * SA + a_c) * 2,                                \
             A + (size_t)(m0 + a_r0) * lda + kt_ + a_c, true);                 \
        cp16(sAb[slot] + ((a_r0 + 64) * SA + a_c) * 2,                         \
             A + (size_t)(m0 + a_r0 + 64) * lda + kt_ + a_c, true);            \
        cp16(sBb[slot] + (b_kr * SB + b_nq) * 2,                               \
             b_ok ? (const void*)(W + (size_t)(kt_ + b_kr) * ldw + n0 + b_nq)  \
                  : (const void*)W, b_ok);                                     \
        asm volatile("cp.async.commit_group;\n");                              \
    } while (0)

    LOAD_TILE(0, 0);
    if (T > 1) LOAD_TILE(1, 1);
    else asm volatile("cp.async.commit_group;\n");

    for (int t = 0; t < T; t++) {
        if (t + 2 < T) { int slot = (t + 2) % 3; LOAD_TILE(slot, t + 2); }
        if (t + 2 < T)      asm volatile("cp.async.wait_group 2;\n");
        else if (t + 1 < T) asm volatile("cp.async.wait_group 1;\n");
        else                asm volatile("cp.async.wait_group 0;\n");
        __syncthreads();

        uint32_t ab = sAb[t % 3], bb = sBb[t % 3];
#pragma unroll
        for (int kb = 0; kb < 32; kb += 16) {
            unsigned af[2][4], bf[2][4];
#pragma unroll
            for (int mt = 0; mt < 2; mt++)
                ldmx4(af[mt], ab + ((wm0 + mt*16 + ln15) * SA + kb + hi8) * 2);
#pragma unroll
            for (int np = 0; np < 2; np++)
                ldmx4t(bf[np], bb + ((kb + ln15) * SB + wn0 + np*16 + hi8) * 2);
#pragma unroll
            for (int mt = 0; mt < 2; mt++)
#pragma unroll
                for (int nt = 0; nt < 4; nt++)
                    mma_bf16(acc[mt][nt], af[mt],
                             bf[nt >> 1][(nt & 1) * 2],
                             bf[nt >> 1][(nt & 1) * 2 + 1]);
        }
        __syncthreads();
    }
#undef LOAD_TILE

    // -------- epilogue: bias (+gelu) (+residual), fp32 or bf16 out --------
#pragma unroll
    for (int mt = 0; mt < 2; mt++) {
        int row0 = m0 + wm0 + mt * 16 + g;
#pragma unroll
        for (int nt = 0; nt < 4; nt++) {
            int col = n0 + wn0 + nt * 8 + cq * 2;
            if (col < N) {
                float b0 = bias[col], b1 = bias[col + 1];
#pragma unroll
                for (int hh = 0; hh < 2; hh++) {
                    int row = row0 + 8 * hh;
                    float v0 = acc[mt][nt][hh * 2 + 0] + b0;
                    float v1 = acc[mt][nt][hh * 2 + 1] + b1;
                    if (act) { v0 = gelu_f(v0); v1 = gelu_f(v1); }
                    if (res) {
                        float2 rr = *(const float2*)&res[(size_t)row * ldc + col];
                        v0 += rr.x; v1 += rr.y;
                    }
                    if (out_bf16) {
                        *(__nv_bfloat162*)&((__nv_bfloat16*)Cc)[(size_t)row * ldc + col] =
                            __float22bfloat162_rn(make_float2(v0, v1));
                    } else {
                        *(float2*)&((float*)Cc)[(size_t)row * ldc + col] =
                            make_float2(v0, v1);
                    }
                }
            }
        }
    }
}

// ---------------------------------------------------------------------------
// Windowed PSA attention.  One block per 8x8 window (2048 windows).
// 384 threads = 64 q-tokens x 6 heads; softmax over 16 kv in registers.
// ---------------------------------------------------------------------------
__global__ __launch_bounds__(384) void attn_kernel(
    const __nv_bfloat16* __restrict__ qkv,
    const float* __restrict__ bias_table,
    __nv_bfloat16* __restrict__ aw)
{
    __shared__ float ks[16][192];
    __shared__ float vs[16][192];
    __shared__ float bt[296];
    int w  = blockIdx.x;
    int b  = w >> 10;
    int wi = w & 1023;
    int wy = wi >> 5, wx = wi & 31;
    int gbase = b*65536 + wy*2048 + wx*8;
    int tid = threadIdx.x;

    for (int i = tid; i < 294; i += 384) bt[i] = bias_table[i];
    for (int i = tid; i < 3072; i += 384) {
        int kt = i / 192, f = i - kt*192;
        int p0 = kt >> 2, p1 = kt & 3;
        int s0 = f / 96;
        int s1 = (f / 48) & 1;
        int c  = f % 48;
        int g  = gbase + (p0*2 + s0)*256 + (p1*2 + s1);
        const __nv_bfloat16* row = qkv + (size_t)g*QKVLD + 192;
        ks[kt][f] = __bfloat162float(row[c]);
        vs[kt][f] = __bfloat162float(row[48 + c]);
    }
    __syncthreads();

    int h  = tid / 64;
    int qt = tid - h*64;
    int qi = qt >> 3, qj = qt & 7;
    int g  = gbase + qi*256 + qj;
    const __nv_bfloat16* qp = qkv + (size_t)g*QKVLD + h*32;
    float q[32];
#pragma unroll
    for (int d = 0; d < 32; d += 8) {
        uint4 raw = *(const uint4*)(qp + d);
        const __nv_bfloat162* p2 = (const __nv_bfloat162*)&raw;
#pragma unroll
        for (int j = 0; j < 4; j++) {
            float2 f2 = __bfloat1622float2(p2[j]);
            q[d + 2*j]     = f2.x * ATT_SCALE;
            q[d + 2*j + 1] = f2.y * ATT_SCALE;
        }
    }
    float sc[16]; float mx = -1e30f;
    int rq0 = (qi >> 1) + 3, rq1 = (qj >> 1) + 3;
#pragma unroll
    for (int kt = 0; kt < 16; kt++) {
        const float* kr = &ks[kt][h*32];
        float s = 0.f;
#pragma unroll
        for (int d = 0; d < 32; d++) s += q[d]*kr[d];
        int rel = (rq0 - (kt >> 2))*7 + rq1 - (kt & 3);
        s += bt[rel*6 + h];
        sc[kt] = s;
        mx = fmaxf(mx, s);
    }
    float sum = 0.f;
#pragma unroll
    for (int kt = 0; kt < 16; kt++) { sc[kt] = __expf(sc[kt] - mx); sum += sc[kt]; }
    float inv = 1.f / sum;
    float o[32];
#pragma unroll
    for (int d = 0; d < 32; d++) o[d] = 0.f;
#pragma unroll
    for (int kt = 0; kt < 16; kt++) {
        float a = sc[kt]*inv;
        const float* vr = &vs[kt][h*32];
#pragma unroll
        for (int d = 0; d < 32; d++) o[d] += a*vr[d];
    }
    __nv_bfloat162* op = (__nv_bfloat162*)(aw + (size_t)g*192 + h*32);
#pragma unroll
    for (int d = 0; d < 32; d += 2)
        op[d >> 1] = __float22bfloat162_rn(make_float2(o[d], o[d+1]));
}

// ---------------------------------------------------------------------------
// Depthwise 5x5 conv + GELU + residual:  out = h1 + gelu(conv(h1) + dwb)
// Issue-optimized: 8 channels/thread, LDG.128 per tap, packed bf16 __hfma2
// accumulation (no converts in the inner loop). 256 threads = 16 tokens x
// 16 channel-octets; weights pre-packed to bf16x2 in smem.
// ---------------------------------------------------------------------------
__global__ __launch_bounds__(256) void dwconv_kernel(
    const __nv_bfloat16* __restrict__ h1, const float* __restrict__ wk,
    const float* __restrict__ wb, __nv_bfloat16* __restrict__ out)
{
    __shared__ __align__(16) uint32_t ws2[25][64];  // bf16x2 per channel pair
    __shared__ float bs[128];
    int cb  = blockIdx.y * 128;
    int tid = threadIdx.x;
    for (int i = tid; i < 1600; i += 256) {
        int k = i >> 6, pp = i & 63;
        __nv_bfloat162 pk = __floats2bfloat162_rn(
            wk[(size_t)(cb + 2*pp)     * 25 + k],
            wk[(size_t)(cb + 2*pp + 1) * 25 + k]);
        ws2[k][pp] = *reinterpret_cast<uint32_t*>(&pk);
    }
    if (tid < 128) bs[tid] = wb[cb + tid];
    __syncthreads();

    int tl = tid >> 4;                  // token in 16-run (same image row)
    int oc = tid & 15;                  // channel octet
    int token = blockIdx.x * 16 + tl;
    int b = token >> 16;
    int p = token & 65535;
    int y = p >> 8, x0 = p & 255;
    int ch = cb + oc * 8;

    __nv_bfloat162 acc[4];
    __nv_bfloat162 z = __float2bfloat162_rn(0.f);
    acc[0] = z; acc[1] = z; acc[2] = z; acc[3] = z;
    uint4 center = make_uint4(0u, 0u, 0u, 0u);
#pragma unroll
    for (int dy = 0; dy < 5; dy++) {
        int yy = y + dy - 2;
        bool yok = (unsigned)yy < 256u;
#pragma unroll
        for (int dx = 0; dx < 5; dx++) {
            int xc = x0 + dx - 2;
            uint4 v = make_uint4(0u, 0u, 0u, 0u);
            if (yok && (unsigned)xc < 256u)
                v = *(const uint4*)&h1[((size_t)(b*65536 + yy*256 + xc))*HID + ch];
            if (dy == 2 && dx == 2) center = v;
            uint4 wv = *(const uint4*)&ws2[dy*5 + dx][oc*4];
            const __nv_bfloat162* vp = reinterpret_cast<const __nv_bfloat162*>(&v);
            const __nv_bfloat162* wp = reinterpret_cast<const __nv_bfloat162*>(&wv);
#pragma unroll
            for (int j = 0; j < 4; j++)
                acc[j] = __hfma2(vp[j], wp[j], acc[j]);
        }
    }

    const __nv_bfloat162* cp = reinterpret_cast<const __nv_bfloat162*>(&center);
    uint4 o;
    __nv_bfloat162* op2 = reinterpret_cast<__nv_bfloat162*>(&o);
#pragma unroll
    for (int j = 0; j < 4; j++) {
        float2 a  = __bfloat1622float2(acc[j]);
        float2 c  = __bfloat1622float2(cp[j]);
        float  b0 = bs[oc*8 + 2*j], b1 = bs[oc*8 + 2*j + 1];
        float2 r;
        r.x = c.x + gelu_f(a.x + b0);
        r.y = c.y + gelu_f(a.y + b1);
        op2[j] = __float22bfloat162_rn(r);
    }
    *(uint4*)&out[(size_t)token*HID + ch] = o;
}

// ---------------------------------------------------------------------------
// Launch sequence (graph-capturable: kernel launches only)
// ---------------------------------------------------------------------------
extern "C" void kernel_launch(void* const* d_in, const int* in_sizes, int n_in,
                              void* d_out, int out_size)
{
    const float* x    = (const float*)d_in[0];
    const float* g1   = (const float*)d_in[1];
    const float* be1  = (const float*)d_in[2];
    const float* wq   = (const float*)d_in[3];
    const float* bq   = (const float*)d_in[4];
    const float* wkv  = (const float*)d_in[5];
    const float* bkv  = (const float*)d_in[6];
    const float* btab = (const float*)d_in[7];
    const float* wproj= (const float*)d_in[8];
    const float* bproj= (const float*)d_in[9];
    const float* g2   = (const float*)d_in[10];
    const float* be2  = (const float*)d_in[11];
    const float* w1f  = (const float*)d_in[12];
    const float* b1f  = (const float*)d_in[13];
    const float* dwk  = (const float*)d_in[14];
    const float* dwb  = (const float*)d_in[15];
    const float* w2f  = (const float*)d_in[16];
    const float* b2f  = (const float*)d_in[17];
    float* out = (float*)d_out;

    __nv_bfloat16 *xn, *qkvb, *aw, *h1, *h, *wb;
    float *x2, *bqkv;
    cudaGetSymbolAddress((void**)&xn,   g_xn);
    cudaGetSymbolAddress((void**)&qkvb, g_qkvb);
    cudaGetSymbolAddress((void**)&aw,   g_aw);
    cudaGetSymbolAddress((void**)&x2,   g_x2);
    cudaGetSymbolAddress((void**)&h1,   g_h1);
    cudaGetSymbolAddress((void**)&h,    g_h);
    cudaGetSymbolAddress((void**)&wb,   g_wb);
    cudaGetSymbolAddress((void**)&bqkv, g_bqkv);

    // 0. Weight/bias prep (bf16, QKV concat)
    prep_kernel<<<(387072 + 255)/256, 256>>>(wq, wkv, wproj, w1f, w2f, wb,
                                             bq, bkv, bqkv);

    // 1. LN1 -> xn (bf16)
    ln_kernel<<<NTOK/8, 256>>>(x, g1, be1, xn);
    // 2. QKV = xn @ wqkv + bqkv  (bf16, ldc=288; N=288 -> 5 n-blocks)
    gemm_bf16_kernel<<<dim3(5, NTOK/128), 256>>>(xn, 192, wb + WB_WQKV, 288, bqkv,
                                                 qkvb, QKVLD, 288, 192,
                                                 nullptr, 0, 1);
    // 3. Window attention -> aw (bf16, token order)
    attn_kernel<<<2048, 384>>>(qkvb, btab, aw);
    // 4. x2 = aw @ wproj + bproj + x  (fp32)
    gemm_bf16_kernel<<<dim3(3, NTOK/128), 256>>>(aw, 192, wb + WB_WPROJ, 192, bproj,
                                                 x2, 192, 192, 192,
                                                 x, 0, 0);
    // 5. LN2 -> xn (bf16)
    ln_kernel<<<NTOK/8, 256>>>(x2, g2, be2, xn);
    // 6. h1 = gelu(xn @ w1f + b1f)  (bf16)
    gemm_bf16_kernel<<<dim3(12, NTOK/128), 256>>>(xn, 192, wb + WB_W1F, HID, b1f,
                                                  h1, HID, HID, 192,
                                                  nullptr, 1, 1);
    // 7. h = h1 + gelu(dwconv(h1) + dwb)  (bf16, packed-HFMA2)
    dwconv_kernel<<<dim3(NTOK/16, 6), 256>>>(h1, dwk, dwb, h);
    // 8. out = h @ w2f + b2f + x2  (fp32)
    gemm_bf16_kernel<<<dim3(3, NTOK/128), 256>>>(h, HID, wb + WB_W2F, 192, b2f,
                                                 out, 192, 192, HID,
                                                 x2, 0, 0);
}

// round 11
// speedup vs baseline: 1.4156x; 1.0375x over previous
#include <cuda_runtime.h>
#include <cuda_bf16.h>
#include <cstdint>
#include <math.h>

// ---------------------------------------------------------------------------
// Problem constants
//   B=2, H=W=256, C=192, HEADS=6, HEAD_DIM=32, WS=8, PW=4, HIDDEN=768
//   NTOK = B*H*W = 131072 tokens
// ---------------------------------------------------------------------------
#define NTOK   131072
#define QKVLD  288      // 192 (q) + 96 (kv) per token, bf16
#define HID    768
#define ATT_SCALE 0.17677669529663688f   // 32^-0.5

// Scratch (static device allocations — no cudaMalloc allowed)
__device__ __align__(16) __nv_bfloat16 g_xn  [(size_t)NTOK * 192]; // LN out
__device__ __align__(16) __nv_bfloat16 g_qkvb[(size_t)NTOK * QKVLD];
__device__ __align__(16) __nv_bfloat16 g_aw  [(size_t)NTOK * 192]; // attn out
__device__ __align__(16) float         g_x2  [(size_t)NTOK * 192]; // resid
__device__ __align__(16) __nv_bfloat16 g_h1  [(size_t)NTOK * HID]; // gelu(fc1)
__device__ __align__(16) __nv_bfloat16 g_h   [(size_t)NTOK * HID]; // ffn hidden
// bf16 weights: wqkv (192x288) | wproj | w1f | w2f
#define WB_WQKV  0
#define WB_WPROJ 55296
#define WB_W1F   92160
#define WB_W2F   239616
__device__ __align__(16) __nv_bfloat16 g_wb[387072];
__device__ __align__(16) float g_bqkv[288];

__device__ __forceinline__ float gelu_f(float v) {
    return 0.5f * v * (1.0f + erff(v * 0.70710678118654752440f));
}

// ---------------------------------------------------------------------------
// Weight/bias prep: concat wq|wkv into 192x288 + convert all weights to bf16
// ---------------------------------------------------------------------------
__global__ __launch_bounds__(256) void prep_kernel(
    const float* __restrict__ wq, const float* __restrict__ wkv,
    const float* __restrict__ wproj, const float* __restrict__ w1f,
    const float* __restrict__ w2f, __nv_bfloat16* __restrict__ wb,
    const float* __restrict__ bq, const float* __restrict__ bkv,
    float* __restrict__ bqkv)
{
    int i = blockIdx.x * 256 + threadIdx.x;
    if (i < 288) bqkv[i] = (i < 192) ? bq[i] : bkv[i - 192];
    if (i >= 387072) return;
    float v;
    if (i < 55296) {
        int row = i / 288, col = i - row * 288;
        v = (col < 192) ? wq[row * 192 + col] : wkv[row * 96 + col - 192];
    } else if (i < 92160) {
        v = wproj[i - 55296];
    } else if (i < 239616) {
        v = w1f[i - 92160];
    } else {
        v = w2f[i - 239616];
    }
    wb[i] = __float2bfloat16(v);
}

// ---------------------------------------------------------------------------
// LayerNorm: one warp per 192-wide row, bf16 output
// ---------------------------------------------------------------------------
__global__ __launch_bounds__(256) void ln_kernel(
    const float* __restrict__ x, const float* __restrict__ g,
    const float* __restrict__ b, __nv_bfloat16* __restrict__ out)
{
    int row  = blockIdx.x * 8 + (threadIdx.x >> 5);
    int lane = threadIdx.x & 31;
    const float* xp = x + (size_t)row * 192;
    float v[6]; float s = 0.f;
#pragma unroll
    for (int i = 0; i < 6; i++) { v[i] = xp[lane + 32*i]; s += v[i]; }
#pragma unroll
    for (int o = 16; o > 0; o >>= 1) s += __shfl_xor_sync(0xffffffffu, s, o);
    float mu = s * (1.f/192.f);
    float var = 0.f;
#pragma unroll
    for (int i = 0; i < 6; i++) { float d = v[i] - mu; var += d*d; }
#pragma unroll
    for (int o = 16; o > 0; o >>= 1) var += __shfl_xor_sync(0xffffffffu, var, o);
    float inv = rsqrtf(var * (1.f/192.f) + 1e-5f);
    __nv_bfloat16* op = out + (size_t)row * 192;
#pragma unroll
    for (int i = 0; i < 6; i++) {
        int c = lane + 32*i;
        op[c] = __float2bfloat16((v[i] - mu) * inv * g[c] + b[c]);
    }
}

// ---------------------------------------------------------------------------
// bf16 tensor-core GEMM, 3-stage cp.async pipeline + ldmatrix.
// Single __syncthreads per K-tile: wait -> sync -> prefetch t+2 -> compute.
// Slot (t+2)%3 == slot (t-1)%3, whose readers all passed this barrier.
//   C[m,n] = act( A[m,:] @ W[:,n] + bias[n] ) (+ res[m,n])
// BM=128, BN=64, BK=32; 256 threads = 8 warps (4m x 2n), warp tile 32x32.
// Requires K >= 64 (T >= 2): true for all uses (K = 192 or 768).
// ---------------------------------------------------------------------------
__device__ __forceinline__ void cp16(uint32_t dst, const void* src, bool ok) {
    int sz = ok ? 16 : 0;
    asm volatile("cp.async.cg.shared.global [%0], [%1], 16, %2;\n"
                 :: "r"(dst), "l"(src), "r"(sz));
}
__device__ __forceinline__ void ldmx4(unsigned r[4], uint32_t addr) {
    asm volatile("ldmatrix.sync.aligned.m8n8.x4.shared.b16 {%0,%1,%2,%3}, [%4];"
                 : "=r"(r[0]), "=r"(r[1]), "=r"(r[2]), "=r"(r[3]) : "r"(addr));
}
__device__ __forceinline__ void ldmx4t(unsigned r[4], uint32_t addr) {
    asm volatile("ldmatrix.sync.aligned.m8n8.x4.trans.shared.b16 {%0,%1,%2,%3}, [%4];"
                 : "=r"(r[0]), "=r"(r[1]), "=r"(r[2]), "=r"(r[3]) : "r"(addr));
}
__device__ __forceinline__ void mma_bf16(float c[4], const unsigned a[4],
                                         unsigned b0, unsigned b1) {
    asm volatile(
        "mma.sync.aligned.m16n8k16.row.col.f32.bf16.bf16.f32 "
        "{%0,%1,%2,%3}, {%4,%5,%6,%7}, {%8,%9}, {%0,%1,%2,%3};"
        : "+f"(c[0]), "+f"(c[1]), "+f"(c[2]), "+f"(c[3])
        : "r"(a[0]), "r"(a[1]), "r"(a[2]), "r"(a[3]), "r"(b0), "r"(b1));
}

#define SA 40
#define SB 72

__global__ __launch_bounds__(256) void gemm_bf16_kernel(
    const __nv_bfloat16* __restrict__ A, int lda,
    const __nv_bfloat16* __restrict__ W, int ldw,
    const float* __restrict__ bias,
    void* __restrict__ Cc, int ldc,
    int N, int K,
    const float* __restrict__ res, int act, int out_bf16)
{
    __shared__ __align__(16) __nv_bfloat16 As[3][128 * SA];
    __shared__ __align__(16) __nv_bfloat16 Bs[3][32 * SB];
    int tid  = threadIdx.x;
    int lane = tid & 31;
    int warp = tid >> 5;
    int m0 = blockIdx.y * 128;
    int n0 = blockIdx.x * 64;
    int wm0 = (warp >> 1) * 32;
    int wn0 = (warp & 1) * 32;
    int g  = lane >> 2, cq = lane & 3;
    int ln15 = lane & 15, hi8 = (lane >> 4) << 3;

    uint32_t sAb[3], sBb[3];
#pragma unroll
    for (int s = 0; s < 3; s++) {
        sAb[s] = (uint32_t)__cvta_generic_to_shared(&As[s][0]);
        sBb[s] = (uint32_t)__cvta_generic_to_shared(&Bs[s][0]);
    }

    float acc[2][4][4];
#pragma unroll
    for (int mt = 0; mt < 2; mt++)
#pragma unroll
        for (int nt = 0; nt < 4; nt++)
#pragma unroll
            for (int r = 0; r < 4; r++) acc[mt][nt][r] = 0.f;

    int a_r0 = tid >> 2, a_c = (tid & 3) << 3;
    int b_kr = tid >> 3, b_nq = (tid & 7) << 3;
    bool b_ok = (n0 + b_nq + 8) <= N;

    int T = K >> 5;
#define LOAD_TILE(slot, t_)                                                    \
    do {                                                                       \
        int kt_ = (t_) << 5;                                                   \
        cp16(sAb[slot] + (a_r0 * SA + a_c) * 2,                                \
             A + (size_t)(m0 + a_r0) * lda + kt_ + a_c, true);                 \
        cp16(sAb[slot] + ((a_r0 + 64) * SA + a_c) * 2,                         \
             A + (size_t)(m0 + a_r0 + 64) * lda + kt_ + a_c, true);            \
        cp16(sBb[slot] + (b_kr * SB + b_nq) * 2,                               \
             b_ok ? (const void*)(W + (size_t)(kt_ + b_kr) * ldw + n0 + b_nq)  \
                  : (const void*)W, b_ok);                                     \
        asm volatile("cp.async.commit_group;\n");                              \
    } while (0)

    LOAD_TILE(0, 0);
    LOAD_TILE(1, 1);

    for (int t = 0; t < T; t++) {
        if (t + 1 < T) asm volatile("cp.async.wait_group 1;\n");
        else           asm volatile("cp.async.wait_group 0;\n");
        __syncthreads();
        if (t + 2 < T) { int slot = (t + 2) % 3; LOAD_TILE(slot, t + 2); }

        uint32_t ab = sAb[t % 3], bb = sBb[t % 3];
#pragma unroll
        for (int kb = 0; kb < 32; kb += 16) {
            unsigned af[2][4], bf[2][4];
#pragma unroll
            for (int mt = 0; mt < 2; mt++)
                ldmx4(af[mt], ab + ((wm0 + mt*16 + ln15) * SA + kb + hi8) * 2);
#pragma unroll
            for (int np = 0; np < 2; np++)
                ldmx4t(bf[np], bb + ((kb + ln15) * SB + wn0 + np*16 + hi8) * 2);
#pragma unroll
            for (int mt = 0; mt < 2; mt++)
#pragma unroll
                for (int nt = 0; nt < 4; nt++)
                    mma_bf16(acc[mt][nt], af[mt],
                             bf[nt >> 1][(nt & 1) * 2],
                             bf[nt >> 1][(nt & 1) * 2 + 1]);
        }
    }
#undef LOAD_TILE

    // -------- epilogue: bias (+gelu) (+residual), fp32 or bf16 out --------
#pragma unroll
    for (int mt = 0; mt < 2; mt++) {
        int row0 = m0 + wm0 + mt * 16 + g;
#pragma unroll
        for (int nt = 0; nt < 4; nt++) {
            int col = n0 + wn0 + nt * 8 + cq * 2;
            if (col < N) {
                float b0 = bias[col], b1 = bias[col + 1];
#pragma unroll
                for (int hh = 0; hh < 2; hh++) {
                    int row = row0 + 8 * hh;
                    float v0 = acc[mt][nt][hh * 2 + 0] + b0;
                    float v1 = acc[mt][nt][hh * 2 + 1] + b1;
                    if (act) { v0 = gelu_f(v0); v1 = gelu_f(v1); }
                    if (res) {
                        float2 rr = *(const float2*)&res[(size_t)row * ldc + col];
                        v0 += rr.x; v1 += rr.y;
                    }
                    if (out_bf16) {
                        *(__nv_bfloat162*)&((__nv_bfloat16*)Cc)[(size_t)row * ldc + col] =
                            __float22bfloat162_rn(make_float2(v0, v1));
                    } else {
                        *(float2*)&((float*)Cc)[(size_t)row * ldc + col] =
                            make_float2(v0, v1);
                    }
                }
            }
        }
    }
}

// ---------------------------------------------------------------------------
// Windowed PSA attention.  One block per 8x8 window (2048 windows).
// 384 threads = 64 q-tokens x 6 heads; softmax over 16 kv in registers.
// Gather: exactly one uint4 (8 bf16) per thread per array; compute loops use
// float4 smem loads (LDS.128) throughout.
// ---------------------------------------------------------------------------
__global__ __launch_bounds__(384) void attn_kernel(
    const __nv_bfloat16* __restrict__ qkv,
    const float* __restrict__ bias_table,
    __nv_bfloat16* __restrict__ aw)
{
    __shared__ float ks[16][192];
    __shared__ float vs[16][192];
    __shared__ float bt[296];
    int w  = blockIdx.x;
    int b  = w >> 10;
    int wi = w & 1023;
    int wy = wi >> 5, wx = wi & 31;
    int gbase = b*65536 + wy*2048 + wx*8;
    int tid = threadIdx.x;

    for (int i = tid; i < 294; i += 384) bt[i] = bias_table[i];
    {
        // 384 items: item = 8 consecutive f of one kv-token row
        int kt = tid / 24;
        int f0 = (tid - kt * 24) * 8;
        int s0 = f0 / 96;
        int s1 = (f0 / 48) & 1;
        int c  = f0 % 48;
        int p0 = kt >> 2, p1 = kt & 3;
        int g  = gbase + (p0*2 + s0)*256 + (p1*2 + s1);
        const __nv_bfloat16* row = qkv + (size_t)g*QKVLD + 192;
        uint4 kraw = *(const uint4*)(row + c);
        uint4 vraw = *(const uint4*)(row + 48 + c);
        const __nv_bfloat162* kp = (const __nv_bfloat162*)&kraw;
        const __nv_bfloat162* vp = (const __nv_bfloat162*)&vraw;
        float4 k0, k1, v0, v1;
        float2 t0 = __bfloat1622float2(kp[0]), t1 = __bfloat1622float2(kp[1]);
        float2 t2 = __bfloat1622float2(kp[2]), t3 = __bfloat1622float2(kp[3]);
        k0 = make_float4(t0.x, t0.y, t1.x, t1.y);
        k1 = make_float4(t2.x, t2.y, t3.x, t3.y);
        t0 = __bfloat1622float2(vp[0]); t1 = __bfloat1622float2(vp[1]);
        t2 = __bfloat1622float2(vp[2]); t3 = __bfloat1622float2(vp[3]);
        v0 = make_float4(t0.x, t0.y, t1.x, t1.y);
        v1 = make_float4(t2.x, t2.y, t3.x, t3.y);
        *(float4*)&ks[kt][f0]     = k0;
        *(float4*)&ks[kt][f0 + 4] = k1;
        *(float4*)&vs[kt][f0]     = v0;
        *(float4*)&vs[kt][f0 + 4] = v1;
    }
    __syncthreads();

    int h  = tid / 64;
    int qt = tid - h*64;
    int qi = qt >> 3, qj = qt & 7;
    int g  = gbase + qi*256 + qj;
    const __nv_bfloat16* qp = qkv + (size_t)g*QKVLD + h*32;
    float4 q4[8];
#pragma unroll
    for (int d = 0; d < 4; d++) {
        uint4 raw = *(const uint4*)(qp + d*8);
        const __nv_bfloat162* p2 = (const __nv_bfloat162*)&raw;
        float2 a0 = __bfloat1622float2(p2[0]);
        float2 a1 = __bfloat1622float2(p2[1]);
        float2 a2 = __bfloat1622float2(p2[2]);
        float2 a3 = __bfloat1622float2(p2[3]);
        q4[d*2]   = make_float4(a0.x*ATT_SCALE, a0.y*ATT_SCALE,
                                a1.x*ATT_SCALE, a1.y*ATT_SCALE);
        q4[d*2+1] = make_float4(a2.x*ATT_SCALE, a2.y*ATT_SCALE,
                                a3.x*ATT_SCALE, a3.y*ATT_SCALE);
    }
    float sc[16]; float mx = -1e30f;
    int rq0 = (qi >> 1) + 3, rq1 = (qj >> 1) + 3;
#pragma unroll
    for (int kt = 0; kt < 16; kt++) {
        const float4* kr = (const float4*)&ks[kt][h*32];
        float s = 0.f;
#pragma unroll
        for (int j = 0; j < 8; j++) {
            float4 kv4 = kr[j];
            s += q4[j].x*kv4.x + q4[j].y*kv4.y + q4[j].z*kv4.z + q4[j].w*kv4.w;
        }
        int rel = (rq0 - (kt >> 2))*7 + rq1 - (kt & 3);
        s += bt[rel*6 + h];
        sc[kt] = s;
        mx = fmaxf(mx, s);
    }
    float sum = 0.f;
#pragma unroll
    for (int kt = 0; kt < 16; kt++) { sc[kt] = __expf(sc[kt] - mx); sum += sc[kt]; }
    float inv = 1.f / sum;
    float4 o4[8];
#pragma unroll
    for (int j = 0; j < 8; j++) o4[j] = make_float4(0.f, 0.f, 0.f, 0.f);
#pragma unroll
    for (int kt = 0; kt < 16; kt++) {
        float a = sc[kt]*inv;
        const float4* vr = (const float4*)&vs[kt][h*32];
#pragma unroll
        for (int j = 0; j < 8; j++) {
            float4 vv = vr[j];
            o4[j].x += a*vv.x; o4[j].y += a*vv.y;
            o4[j].z += a*vv.z; o4[j].w += a*vv.w;
        }
    }
    __nv_bfloat16* op = aw + (size_t)g*192 + h*32;
#pragma unroll
    for (int j = 0; j < 4; j++) {
        uint4 o;
        __nv_bfloat162* o2 = (__nv_bfloat162*)&o;
        o2[0] = __float22bfloat162_rn(make_float2(o4[j*2].x,   o4[j*2].y));
        o2[1] = __float22bfloat162_rn(make_float2(o4[j*2].z,   o4[j*2].w));
        o2[2] = __float22bfloat162_rn(make_float2(o4[j*2+1].x, o4[j*2+1].y));
        o2[3] = __float22bfloat162_rn(make_float2(o4[j*2+1].z, o4[j*2+1].w));
        *(uint4*)(op + j*8) = o;
    }
}

// ---------------------------------------------------------------------------
// Depthwise 5x5 conv + GELU + residual:  out = h1 + gelu(conv(h1) + dwb)
// 8 channels/thread, LDG.128 per tap, packed bf16 __hfma2 accumulation.
// ---------------------------------------------------------------------------
__global__ __launch_bounds__(256) void dwconv_kernel(
    const __nv_bfloat16* __restrict__ h1, const float* __restrict__ wk,
    const float* __restrict__ wb, __nv_bfloat16* __restrict__ out)
{
    __shared__ __align__(16) uint32_t ws2[25][64];  // bf16x2 per channel pair
    __shared__ float bs[128];
    int cb  = blockIdx.y * 128;
    int tid = threadIdx.x;
    for (int i = tid; i < 1600; i += 256) {
        int k = i >> 6, pp = i & 63;
        __nv_bfloat162 pk = __floats2bfloat162_rn(
            wk[(size_t)(cb + 2*pp)     * 25 + k],
            wk[(size_t)(cb + 2*pp + 1) * 25 + k]);
        ws2[k][pp] = *reinterpret_cast<uint32_t*>(&pk);
    }
    if (tid < 128) bs[tid] = wb[cb + tid];
    __syncthreads();

    int tl = tid >> 4;
    int oc = tid & 15;
    int token = blockIdx.x * 16 + tl;
    int b = token >> 16;
    int p = token & 65535;
    int y = p >> 8, x0 = p & 255;
    int ch = cb + oc * 8;

    __nv_bfloat162 acc[4];
    __nv_bfloat162 z = __float2bfloat162_rn(0.f);
    acc[0] = z; acc[1] = z; acc[2] = z; acc[3] = z;
    uint4 center = make_uint4(0u, 0u, 0u, 0u);
#pragma unroll
    for (int dy = 0; dy < 5; dy++) {
        int yy = y + dy - 2;
        bool yok = (unsigned)yy < 256u;
#pragma unroll
        for (int dx = 0; dx < 5; dx++) {
            int xc = x0 + dx - 2;
            uint4 v = make_uint4(0u, 0u, 0u, 0u);
            if (yok && (unsigned)xc < 256u)
                v = *(const uint4*)&h1[((size_t)(b*65536 + yy*256 + xc))*HID + ch];
            if (dy == 2 && dx == 2) center = v;
            uint4 wv = *(const uint4*)&ws2[dy*5 + dx][oc*4];
            const __nv_bfloat162* vp = reinterpret_cast<const __nv_bfloat162*>(&v);
            const __nv_bfloat162* wp = reinterpret_cast<const __nv_bfloat162*>(&wv);
#pragma unroll
            for (int j = 0; j < 4; j++)
                acc[j] = __hfma2(vp[j], wp[j], acc[j]);
        }
    }

    const __nv_bfloat162* cp = reinterpret_cast<const __nv_bfloat162*>(&center);
    uint4 o;
    __nv_bfloat162* op2 = reinterpret_cast<__nv_bfloat162*>(&o);
#pragma unroll
    for (int j = 0; j < 4; j++) {
        float2 a  = __bfloat1622float2(acc[j]);
        float2 c  = __bfloat1622float2(cp[j]);
        float  b0 = bs[oc*8 + 2*j], b1 = bs[oc*8 + 2*j + 1];
        float2 r;
        r.x = c.x + gelu_f(a.x + b0);
        r.y = c.y + gelu_f(a.y + b1);
        op2[j] = __float22bfloat162_rn(r);
    }
    *(uint4*)&out[(size_t)token*HID + ch] = o;
}

// ---------------------------------------------------------------------------
// Launch sequence (graph-capturable: kernel launches only)
// ---------------------------------------------------------------------------
extern "C" void kernel_launch(void* const* d_in, const int* in_sizes, int n_in,
                              void* d_out, int out_size)
{
    const float* x    = (const float*)d_in[0];
    const float* g1   = (const float*)d_in[1];
    const float* be1  = (const float*)d_in[2];
    const float* wq   = (const float*)d_in[3];
    const float* bq   = (const float*)d_in[4];
    const float* wkv  = (const float*)d_in[5];
    const float* bkv  = (const float*)d_in[6];
    const float* btab = (const float*)d_in[7];
    const float* wproj= (const float*)d_in[8];
    const float* bproj= (const float*)d_in[9];
    const float* g2   = (const float*)d_in[10];
    const float* be2  = (const float*)d_in[11];
    const float* w1f  = (const float*)d_in[12];
    const float* b1f  = (const float*)d_in[13];
    const float* dwk  = (const float*)d_in[14];
    const float* dwb  = (const float*)d_in[15];
    const float* w2f  = (const float*)d_in[16];
    const float* b2f  = (const float*)d_in[17];
    float* out = (float*)d_out;

    __nv_bfloat16 *xn, *qkvb, *aw, *h1, *h, *wb;
    float *x2, *bqkv;
    cudaGetSymbolAddress((void**)&xn,   g_xn);
    cudaGetSymbolAddress((void**)&qkvb, g_qkvb);
    cudaGetSymbolAddress((void**)&aw,   g_aw);
    cudaGetSymbolAddress((void**)&x2,   g_x2);
    cudaGetSymbolAddress((void**)&h1,   g_h1);
    cudaGetSymbolAddress((void**)&h,    g_h);
    cudaGetSymbolAddress((void**)&wb,   g_wb);
    cudaGetSymbolAddress((void**)&bqkv, g_bqkv);

    // 0. Weight/bias prep (bf16, QKV concat)
    prep_kernel<<<(387072 + 255)/256, 256>>>(wq, wkv, wproj, w1f, w2f, wb,
                                             bq, bkv, bqkv);

    // 1. LN1 -> xn (bf16)
    ln_kernel<<<NTOK/8, 256>>>(x, g1, be1, xn);
    // 2. QKV = xn @ wqkv + bqkv  (bf16, ldc=288; N=288 -> 5 n-blocks)
    gemm_bf16_kernel<<<dim3(5, NTOK/128), 256>>>(xn, 192, wb + WB_WQKV, 288, bqkv,
                                                 qkvb, QKVLD, 288, 192,
                                                 nullptr, 0, 1);
    // 3. Window attention -> aw (bf16, token order)
    attn_kernel<<<2048, 384>>>(qkvb, btab, aw);
    // 4. x2 = aw @ wproj + bproj + x  (fp32)
    gemm_bf16_kernel<<<dim3(3, NTOK/128), 256>>>(aw, 192, wb + WB_WPROJ, 192, bproj,
                                                 x2, 192, 192, 192,
                                                 x, 0, 0);
    // 5. LN2 -> xn (bf16)
    ln_kernel<<<NTOK/8, 256>>>(x2, g2, be2, xn);
    // 6. h1 = gelu(xn @ w1f + b1f)  (bf16)
    gemm_bf16_kernel<<<dim3(12, NTOK/128), 256>>>(xn, 192, wb + WB_W1F, HID, b1f,
                                                  h1, HID, HID, 192,
                                                  nullptr, 1, 1);
    // 7. h = h1 + gelu(dwconv(h1) + dwb)  (bf16, packed-HFMA2)
    dwconv_kernel<<<dim3(NTOK/16, 6), 256>>>(h1, dwk, dwb, h);
    // 8. out = h @ w2f + b2f + x2  (fp32)
    gemm_bf16_kernel<<<dim3(3, NTOK/128), 256>>>(h, HID, wb + WB_W2F, 192, b2f,
                                                 out, 192, 192, HID,
                                                 x2, 0, 0);
}

// round 12
// speedup vs baseline: 1.5220x; 1.0752x over previous
#include <cuda_runtime.h>
#include <cuda_bf16.h>
#include <cstdint>
#include <math.h>

// ---------------------------------------------------------------------------
// Problem constants
//   B=2, H=W=256, C=192, HEADS=6, HEAD_DIM=32, WS=8, PW=4, HIDDEN=768
//   NTOK = B*H*W = 131072 tokens
// ---------------------------------------------------------------------------
#define NTOK   131072
#define QKVLD  288      // 192 (q) + 96 (kv) per token, bf16
#define HID    768
#define ATT_SCALE 0.17677669529663688f   // 32^-0.5

// Scratch (static device allocations — no cudaMalloc allowed)
__device__ __align__(16) __nv_bfloat16 g_xn  [(size_t)NTOK * 192]; // LN out
__device__ __align__(16) __nv_bfloat16 g_qkvb[(size_t)NTOK * QKVLD];
__device__ __align__(16) __nv_bfloat16 g_aw  [(size_t)NTOK * 192]; // attn out
__device__ __align__(16) float         g_x2  [(size_t)NTOK * 192]; // resid
__device__ __align__(16) __nv_bfloat16 g_h1  [(size_t)NTOK * HID]; // gelu(fc1)
__device__ __align__(16) __nv_bfloat16 g_h   [(size_t)NTOK * HID]; // ffn hidden
// bf16 weights: wqkv (192x288) | wproj | w1f | w2f
#define WB_WQKV  0
#define WB_WPROJ 55296
#define WB_W1F   92160
#define WB_W2F   239616
__device__ __align__(16) __nv_bfloat16 g_wb[387072];
__device__ __align__(16) float g_bqkv[288];

__device__ __forceinline__ float gelu_f(float v) {
    return 0.5f * v * (1.0f + erff(v * 0.70710678118654752440f));
}

// ---------------------------------------------------------------------------
// Weight/bias prep: concat wq|wkv into 192x288 + convert all weights to bf16
// ---------------------------------------------------------------------------
__global__ __launch_bounds__(256) void prep_kernel(
    const float* __restrict__ wq, const float* __restrict__ wkv,
    const float* __restrict__ wproj, const float* __restrict__ w1f,
    const float* __restrict__ w2f, __nv_bfloat16* __restrict__ wb,
    const float* __restrict__ bq, const float* __restrict__ bkv,
    float* __restrict__ bqkv)
{
    int i = blockIdx.x * 256 + threadIdx.x;
    if (i < 288) bqkv[i] = (i < 192) ? bq[i] : bkv[i - 192];
    if (i >= 387072) return;
    float v;
    if (i < 55296) {
        int row = i / 288, col = i - row * 288;
        v = (col < 192) ? wq[row * 192 + col] : wkv[row * 96 + col - 192];
    } else if (i < 92160) {
        v = wproj[i - 55296];
    } else if (i < 239616) {
        v = w1f[i - 92160];
    } else {
        v = w2f[i - 239616];
    }
    wb[i] = __float2bfloat16(v);
}

// ---------------------------------------------------------------------------
// LayerNorm: one warp per 192-wide row, bf16 output
// ---------------------------------------------------------------------------
__global__ __launch_bounds__(256) void ln_kernel(
    const float* __restrict__ x, const float* __restrict__ g,
    const float* __restrict__ b, __nv_bfloat16* __restrict__ out)
{
    int row  = blockIdx.x * 8 + (threadIdx.x >> 5);
    int lane = threadIdx.x & 31;
    const float* xp = x + (size_t)row * 192;
    float v[6]; float s = 0.f;
#pragma unroll
    for (int i = 0; i < 6; i++) { v[i] = xp[lane + 32*i]; s += v[i]; }
#pragma unroll
    for (int o = 16; o > 0; o >>= 1) s += __shfl_xor_sync(0xffffffffu, s, o);
    float mu = s * (1.f/192.f);
    float var = 0.f;
#pragma unroll
    for (int i = 0; i < 6; i++) { float d = v[i] - mu; var += d*d; }
#pragma unroll
    for (int o = 16; o > 0; o >>= 1) var += __shfl_xor_sync(0xffffffffu, var, o);
    float inv = rsqrtf(var * (1.f/192.f) + 1e-5f);
    __nv_bfloat16* op = out + (size_t)row * 192;
#pragma unroll
    for (int i = 0; i < 6; i++) {
        int c = lane + 32*i;
        op[c] = __float2bfloat16((v[i] - mu) * inv * g[c] + b[c]);
    }
}

// ---------------------------------------------------------------------------
// bf16 tensor-core GEMM, 3-stage cp.async pipeline + ldmatrix.
// Mainloop unrolled modulo 3: every smem slot index is a compile-time
// constant (no register-indexed slot selection, minimal address ALU).
// REQUIRES K % 96 == 0 (T = K/32 divisible by 3): K = 192 or 768 here.
//   C[m,n] = act( A[m,:] @ W[:,n] + bias[n] ) (+ res[m,n])
// BM=128, BN=64, BK=32; 256 threads = 8 warps (4m x 2n), warp tile 32x32.
// ---------------------------------------------------------------------------
__device__ __forceinline__ void cp16(uint32_t dst, const void* src, bool ok) {
    int sz = ok ? 16 : 0;
    asm volatile("cp.async.cg.shared.global [%0], [%1], 16, %2;\n"
                 :: "r"(dst), "l"(src), "r"(sz));
}
__device__ __forceinline__ void ldmx4(unsigned r[4], uint32_t addr) {
    asm volatile("ldmatrix.sync.aligned.m8n8.x4.shared.b16 {%0,%1,%2,%3}, [%4];"
                 : "=r"(r[0]), "=r"(r[1]), "=r"(r[2]), "=r"(r[3]) : "r"(addr));
}
__device__ __forceinline__ void ldmx4t(unsigned r[4], uint32_t addr) {
    asm volatile("ldmatrix.sync.aligned.m8n8.x4.trans.shared.b16 {%0,%1,%2,%3}, [%4];"
                 : "=r"(r[0]), "=r"(r[1]), "=r"(r[2]), "=r"(r[3]) : "r"(addr));
}
__device__ __forceinline__ void mma_bf16(float c[4], const unsigned a[4],
                                         unsigned b0, unsigned b1) {
    asm volatile(
        "mma.sync.aligned.m16n8k16.row.col.f32.bf16.bf16.f32 "
        "{%0,%1,%2,%3}, {%4,%5,%6,%7}, {%8,%9}, {%0,%1,%2,%3};"
        : "+f"(c[0]), "+f"(c[1]), "+f"(c[2]), "+f"(c[3])
        : "r"(a[0]), "r"(a[1]), "r"(a[2]), "r"(a[3]), "r"(b0), "r"(b1));
}

#define SA 40
#define SB 72

__global__ __launch_bounds__(256) void gemm_bf16_kernel(
    const __nv_bfloat16* __restrict__ A, int lda,
    const __nv_bfloat16* __restrict__ W, int ldw,
    const float* __restrict__ bias,
    void* __restrict__ Cc, int ldc,
    int N, int K,
    const float* __restrict__ res, int act, int out_bf16)
{
    __shared__ __align__(16) __nv_bfloat16 As[3][128 * SA];
    __shared__ __align__(16) __nv_bfloat16 Bs[3][32 * SB];
    int tid  = threadIdx.x;
    int lane = tid & 31;
    int warp = tid >> 5;
    int m0 = blockIdx.y * 128;
    int n0 = blockIdx.x * 64;
    int wm0 = (warp >> 1) * 32;
    int wn0 = (warp & 1) * 32;
    int g  = lane >> 2, cq = lane & 3;
    int ln15 = lane & 15, hi8 = (lane >> 4) << 3;

    uint32_t sAb[3], sBb[3];
#pragma unroll
    for (int s = 0; s < 3; s++) {
        sAb[s] = (uint32_t)__cvta_generic_to_shared(&As[s][0]);
        sBb[s] = (uint32_t)__cvta_generic_to_shared(&Bs[s][0]);
    }

    float acc[2][4][4];
#pragma unroll
    for (int mt = 0; mt < 2; mt++)
#pragma unroll
        for (int nt = 0; nt < 4; nt++)
#pragma unroll
            for (int r = 0; r < 4; r++) acc[mt][nt][r] = 0.f;

    int a_r0 = tid >> 2, a_c = (tid & 3) << 3;
    int b_kr = tid >> 3, b_nq = (tid & 7) << 3;
    bool b_ok = (n0 + b_nq + 8) <= N;

    int T = K >> 5;   // divisible by 3 for all uses
#define LOAD_TILE(slot, t_)                                                    \
    do {                                                                       \
        int kt_ = (t_) << 5;                                                   \
        cp16(sAb[slot] + (a_r0 * SA + a_c) * 2,                                \
             A + (size_t)(m0 + a_r0) * lda + kt_ + a_c, true);                 \
        cp16(sAb[slot] + ((a_r0 + 64) * SA + a_c) * 2,                         \
             A + (size_t)(m0 + a_r0 + 64) * lda + kt_ + a_c, true);            \
        cp16(sBb[slot] + (b_kr * SB + b_nq) * 2,                               \
             b_ok ? (const void*)(W + (size_t)(kt_ + b_kr) * ldw + n0 + b_nq)  \
                  : (const void*)W, b_ok);                                     \
        asm volatile("cp.async.commit_group;\n");                              \
    } while (0)

#define COMPUTE(slot)                                                          \
    do {                                                                       \
        uint32_t ab = sAb[slot], bb = sBb[slot];                               \
        _Pragma("unroll")                                                      \
        for (int kb = 0; kb < 32; kb += 16) {                                  \
            unsigned af[2][4], bf[2][4];                                       \
            _Pragma("unroll")                                                  \
            for (int mt = 0; mt < 2; mt++)                                     \
                ldmx4(af[mt], ab + ((wm0 + mt*16 + ln15) * SA + kb + hi8) * 2);\
            _Pragma("unroll")                                                  \
            for (int np = 0; np < 2; np++)                                     \
                ldmx4t(bf[np], bb + ((kb + ln15) * SB + wn0 + np*16 + hi8) * 2);\
            _Pragma("unroll")                                                  \
            for (int mt = 0; mt < 2; mt++)                                     \
                _Pragma("unroll")                                              \
                for (int nt = 0; nt < 4; nt++)                                 \
                    mma_bf16(acc[mt][nt], af[mt],                              \
                             bf[nt >> 1][(nt & 1) * 2],                        \
                             bf[nt >> 1][(nt & 1) * 2 + 1]);                   \
        }                                                                      \
    } while (0)

#define STEP(slot, nslot, t_)                                                  \
    do {                                                                       \
        if ((t_) + 1 < T) asm volatile("cp.async.wait_group 1;\n");            \
        else              asm volatile("cp.async.wait_group 0;\n");            \
        __syncthreads();                                                       \
        if ((t_) + 2 < T) LOAD_TILE(nslot, (t_) + 2);                          \
        COMPUTE(slot);                                                         \
    } while (0)

    LOAD_TILE(0, 0);
    LOAD_TILE(1, 1);
    for (int t = 0; t < T; t += 3) {
        STEP(0, 2, t);
        STEP(1, 0, t + 1);
        STEP(2, 1, t + 2);
    }
#undef STEP
#undef COMPUTE
#undef LOAD_TILE

    // -------- epilogue: bias (+gelu) (+residual), fp32 or bf16 out --------
#pragma unroll
    for (int mt = 0; mt < 2; mt++) {
        int row0 = m0 + wm0 + mt * 16 + g;
#pragma unroll
        for (int nt = 0; nt < 4; nt++) {
            int col = n0 + wn0 + nt * 8 + cq * 2;
            if (col < N) {
                float b0 = bias[col], b1 = bias[col + 1];
#pragma unroll
                for (int hh = 0; hh < 2; hh++) {
                    int row = row0 + 8 * hh;
                    float v0 = acc[mt][nt][hh * 2 + 0] + b0;
                    float v1 = acc[mt][nt][hh * 2 + 1] + b1;
                    if (act) { v0 = gelu_f(v0); v1 = gelu_f(v1); }
                    if (res) {
                        float2 rr = *(const float2*)&res[(size_t)row * ldc + col];
                        v0 += rr.x; v1 += rr.y;
                    }
                    if (out_bf16) {
                        *(__nv_bfloat162*)&((__nv_bfloat16*)Cc)[(size_t)row * ldc + col] =
                            __float22bfloat162_rn(make_float2(v0, v1));
                    } else {
                        *(float2*)&((float*)Cc)[(size_t)row * ldc + col] =
                            make_float2(v0, v1);
                    }
                }
            }
        }
    }
}

// ---------------------------------------------------------------------------
// Windowed PSA attention.  One block per 8x8 window (2048 windows).
// 384 threads = 64 q-tokens x 6 heads; softmax over 16 kv in registers.
// Gather: one uint4 per thread per array; compute on float4 smem loads.
// ---------------------------------------------------------------------------
__global__ __launch_bounds__(384) void attn_kernel(
    const __nv_bfloat16* __restrict__ qkv,
    const float* __restrict__ bias_table,
    __nv_bfloat16* __restrict__ aw)
{
    __shared__ float ks[16][192];
    __shared__ float vs[16][192];
    __shared__ float bt[296];
    int w  = blockIdx.x;
    int b  = w >> 10;
    int wi = w & 1023;
    int wy = wi >> 5, wx = wi & 31;
    int gbase = b*65536 + wy*2048 + wx*8;
    int tid = threadIdx.x;

    for (int i = tid; i < 294; i += 384) bt[i] = bias_table[i];
    {
        int kt = tid / 24;
        int f0 = (tid - kt * 24) * 8;
        int s0 = f0 / 96;
        int s1 = (f0 / 48) & 1;
        int c  = f0 % 48;
        int p0 = kt >> 2, p1 = kt & 3;
        int g  = gbase + (p0*2 + s0)*256 + (p1*2 + s1);
        const __nv_bfloat16* row = qkv + (size_t)g*QKVLD + 192;
        uint4 kraw = *(const uint4*)(row + c);
        uint4 vraw = *(const uint4*)(row + 48 + c);
        const __nv_bfloat162* kp = (const __nv_bfloat162*)&kraw;
        const __nv_bfloat162* vp = (const __nv_bfloat162*)&vraw;
        float2 t0 = __bfloat1622float2(kp[0]), t1 = __bfloat1622float2(kp[1]);
        float2 t2 = __bfloat1622float2(kp[2]), t3 = __bfloat1622float2(kp[3]);
        *(float4*)&ks[kt][f0]     = make_float4(t0.x, t0.y, t1.x, t1.y);
        *(float4*)&ks[kt][f0 + 4] = make_float4(t2.x, t2.y, t3.x, t3.y);
        t0 = __bfloat1622float2(vp[0]); t1 = __bfloat1622float2(vp[1]);
        t2 = __bfloat1622float2(vp[2]); t3 = __bfloat1622float2(vp[3]);
        *(float4*)&vs[kt][f0]     = make_float4(t0.x, t0.y, t1.x, t1.y);
        *(float4*)&vs[kt][f0 + 4] = make_float4(t2.x, t2.y, t3.x, t3.y);
    }
    __syncthreads();

    int h  = tid / 64;
    int qt = tid - h*64;
    int qi = qt >> 3, qj = qt & 7;
    int g  = gbase + qi*256 + qj;
    const __nv_bfloat16* qp = qkv + (size_t)g*QKVLD + h*32;
    float4 q4[8];
#pragma unroll
    for (int d = 0; d < 4; d++) {
        uint4 raw = *(const uint4*)(qp + d*8);
        const __nv_bfloat162* p2 = (const __nv_bfloat162*)&raw;
        float2 a0 = __bfloat1622float2(p2[0]);
        float2 a1 = __bfloat1622float2(p2[1]);
        float2 a2 = __bfloat1622float2(p2[2]);
        float2 a3 = __bfloat1622float2(p2[3]);
        q4[d*2]   = make_float4(a0.x*ATT_SCALE, a0.y*ATT_SCALE,
                                a1.x*ATT_SCALE, a1.y*ATT_SCALE);
        q4[d*2+1] = make_float4(a2.x*ATT_SCALE, a2.y*ATT_SCALE,
                                a3.x*ATT_SCALE, a3.y*ATT_SCALE);
    }
    float sc[16]; float mx = -1e30f;
    int rq0 = (qi >> 1) + 3, rq1 = (qj >> 1) + 3;
#pragma unroll
    for (int kt = 0; kt < 16; kt++) {
        const float4* kr = (const float4*)&ks[kt][h*32];
        float s = 0.f;
#pragma unroll
        for (int j = 0; j < 8; j++) {
            float4 kv4 = kr[j];
            s += q4[j].x*kv4.x + q4[j].y*kv4.y + q4[j].z*kv4.z + q4[j].w*kv4.w;
        }
        int rel = (rq0 - (kt >> 2))*7 + rq1 - (kt & 3);
        s += bt[rel*6 + h];
        sc[kt] = s;
        mx = fmaxf(mx, s);
    }
    float sum = 0.f;
#pragma unroll
    for (int kt = 0; kt < 16; kt++) { sc[kt] = __expf(sc[kt] - mx); sum += sc[kt]; }
    float inv = 1.f / sum;
    float4 o4[8];
#pragma unroll
    for (int j = 0; j < 8; j++) o4[j] = make_float4(0.f, 0.f, 0.f, 0.f);
#pragma unroll
    for (int kt = 0; kt < 16; kt++) {
        float a = sc[kt]*inv;
        const float4* vr = (const float4*)&vs[kt][h*32];
#pragma unroll
        for (int j = 0; j < 8; j++) {
            float4 vv = vr[j];
            o4[j].x += a*vv.x; o4[j].y += a*vv.y;
            o4[j].z += a*vv.z; o4[j].w += a*vv.w;
        }
    }
    __nv_bfloat16* op = aw + (size_t)g*192 + h*32;
#pragma unroll
    for (int j = 0; j < 4; j++) {
        uint4 o;
        __nv_bfloat162* o2 = (__nv_bfloat162*)&o;
        o2[0] = __float22bfloat162_rn(make_float2(o4[j*2].x,   o4[j*2].y));
        o2[1] = __float22bfloat162_rn(make_float2(o4[j*2].z,   o4[j*2].w));
        o2[2] = __float22bfloat162_rn(make_float2(o4[j*2+1].x, o4[j*2+1].y));
        o2[3] = __float22bfloat162_rn(make_float2(o4[j*2+1].z, o4[j*2+1].w));
        *(uint4*)(op + j*8) = o;
    }
}

// ---------------------------------------------------------------------------
// Depthwise 5x5 conv + GELU + residual:  out = h1 + gelu(conv(h1) + dwb)
// 8 channels/thread, LDG.128 per tap, packed bf16 __hfma2 accumulation.
// ---------------------------------------------------------------------------
__global__ __launch_bounds__(256) void dwconv_kernel(
    const __nv_bfloat16* __restrict__ h1, const float* __restrict__ wk,
    const float* __restrict__ wb, __nv_bfloat16* __restrict__ out)
{
    __shared__ __align__(16) uint32_t ws2[25][64];  // bf16x2 per channel pair
    __shared__ float bs[128];
    int cb  = blockIdx.y * 128;
    int tid = threadIdx.x;
    for (int i = tid; i < 1600; i += 256) {
        int k = i >> 6, pp = i & 63;
        __nv_bfloat162 pk = __floats2bfloat162_rn(
            wk[(size_t)(cb + 2*pp)     * 25 + k],
            wk[(size_t)(cb + 2*pp + 1) * 25 + k]);
        ws2[k][pp] = *reinterpret_cast<uint32_t*>(&pk);
    }
    if (tid < 128) bs[tid] = wb[cb + tid];
    __syncthreads();

    int tl = tid >> 4;
    int oc = tid & 15;
    int token = blockIdx.x * 16 + tl;
    int b = token >> 16;
    int p = token & 65535;
    int y = p >> 8, x0 = p & 255;
    int ch = cb + oc * 8;

    __nv_bfloat162 acc[4];
    __nv_bfloat162 z = __float2bfloat162_rn(0.f);
    acc[0] = z; acc[1] = z; acc[2] = z; acc[3] = z;
    uint4 center = make_uint4(0u, 0u, 0u, 0u);
#pragma unroll
    for (int dy = 0; dy < 5; dy++) {
        int yy = y + dy - 2;
        bool yok = (unsigned)yy < 256u;
#pragma unroll
        for (int dx = 0; dx < 5; dx++) {
            int xc = x0 + dx - 2;
            uint4 v = make_uint4(0u, 0u, 0u, 0u);
            if (yok && (unsigned)xc < 256u)
                v = *(const uint4*)&h1[((size_t)(b*65536 + yy*256 + xc))*HID + ch];
            if (dy == 2 && dx == 2) center = v;
            uint4 wv = *(const uint4*)&ws2[dy*5 + dx][oc*4];
            const __nv_bfloat162* vp = reinterpret_cast<const __nv_bfloat162*>(&v);
            const __nv_bfloat162* wp = reinterpret_cast<const __nv_bfloat162*>(&wv);
#pragma unroll
            for (int j = 0; j < 4; j++)
                acc[j] = __hfma2(vp[j], wp[j], acc[j]);
        }
    }

    const __nv_bfloat162* cp = reinterpret_cast<const __nv_bfloat162*>(&center);
    uint4 o;
    __nv_bfloat162* op2 = reinterpret_cast<__nv_bfloat162*>(&o);
#pragma unroll
    for (int j = 0; j < 4; j++) {
        float2 a  = __bfloat1622float2(acc[j]);
        float2 c  = __bfloat1622float2(cp[j]);
        float  b0 = bs[oc*8 + 2*j], b1 = bs[oc*8 + 2*j + 1];
        float2 r;
        r.x = c.x + gelu_f(a.x + b0);
        r.y = c.y + gelu_f(a.y + b1);
        op2[j] = __float22bfloat162_rn(r);
    }
    *(uint4*)&out[(size_t)token*HID + ch] = o;
}

// ---------------------------------------------------------------------------
// Launch sequence (graph-capturable: kernel launches only)
// ---------------------------------------------------------------------------
extern "C" void kernel_launch(void* const* d_in, const int* in_sizes, int n_in,
                              void* d_out, int out_size)
{
    const float* x    = (const float*)d_in[0];
    const float* g1   = (const float*)d_in[1];
    const float* be1  = (const float*)d_in[2];
    const float* wq   = (const float*)d_in[3];
    const float* bq   = (const float*)d_in[4];
    const float* wkv  = (const float*)d_in[5];
    const float* bkv  = (const float*)d_in[6];
    const float* btab = (const float*)d_in[7];
    const float* wproj= (const float*)d_in[8];
    const float* bproj= (const float*)d_in[9];
    const float* g2   = (const float*)d_in[10];
    const float* be2  = (const float*)d_in[11];
    const float* w1f  = (const float*)d_in[12];
    const float* b1f  = (const float*)d_in[13];
    const float* dwk  = (const float*)d_in[14];
    const float* dwb  = (const float*)d_in[15];
    const float* w2f  = (const float*)d_in[16];
    const float* b2f  = (const float*)d_in[17];
    float* out = (float*)d_out;

    __nv_bfloat16 *xn, *qkvb, *aw, *h1, *h, *wb;
    float *x2, *bqkv;
    cudaGetSymbolAddress((void**)&xn,   g_xn);
    cudaGetSymbolAddress((void**)&qkvb, g_qkvb);
    cudaGetSymbolAddress((void**)&aw,   g_aw);
    cudaGetSymbolAddress((void**)&x2,   g_x2);
    cudaGetSymbolAddress((void**)&h1,   g_h1);
    cudaGetSymbolAddress((void**)&h,    g_h);
    cudaGetSymbolAddress((void**)&wb,   g_wb);
    cudaGetSymbolAddress((void**)&bqkv, g_bqkv);

    // 0. Weight/bias prep (bf16, QKV concat)
    prep_kernel<<<(387072 + 255)/256, 256>>>(wq, wkv, wproj, w1f, w2f, wb,
                                             bq, bkv, bqkv);

    // 1. LN1 -> xn (bf16)
    ln_kernel<<<NTOK/8, 256>>>(x, g1, be1, xn);
    // 2. QKV = xn @ wqkv + bqkv  (bf16, ldc=288; N=288 -> 5 n-blocks)
    gemm_bf16_kernel<<<dim3(5, NTOK/128), 256>>>(xn, 192, wb + WB_WQKV, 288, bqkv,
                                                 qkvb, QKVLD, 288, 192,
                                                 nullptr, 0, 1);
    // 3. Window attention -> aw (bf16, token order)
    attn_kernel<<<2048, 384>>>(qkvb, btab, aw);
    // 4. x2 = aw @ wproj + bproj + x  (fp32)
    gemm_bf16_kernel<<<dim3(3, NTOK/128), 256>>>(aw, 192, wb + WB_WPROJ, 192, bproj,
                                                 x2, 192, 192, 192,
                                                 x, 0, 0);
    // 5. LN2 -> xn (bf16)
    ln_kernel<<<NTOK/8, 256>>>(x2, g2, be2, xn);
    // 6. h1 = gelu(xn @ w1f + b1f)  (bf16)
    gemm_bf16_kernel<<<dim3(12, NTOK/128), 256>>>(xn, 192, wb + WB_W1F, HID, b1f,
                                                  h1, HID, HID, 192,
                                                  nullptr, 1, 1);
    // 7. h = h1 + gelu(dwconv(h1) + dwb)  (bf16, packed-HFMA2)
    dwconv_kernel<<<dim3(NTOK/16, 6), 256>>>(h1, dwk, dwb, h);
    // 8. out = h @ w2f + b2f + x2  (fp32)
    gemm_bf16_kernel<<<dim3(3, NTOK/128), 256>>>(h, HID, wb + WB_W2F, 192, b2f,
                                                 out, 192, 192, HID,
                                                 x2, 0, 0);
}

// round 13
// speedup vs baseline: 1.7140x; 1.1261x over previous
#include <cuda_runtime.h>
#include <cuda_bf16.h>
#include <cstdint>
#include <math.h>

// ---------------------------------------------------------------------------
// Problem constants
//   B=2, H=W=256, C=192, HEADS=6, HEAD_DIM=32, WS=8, PW=4, HIDDEN=768
//   NTOK = B*H*W = 131072 tokens
// ---------------------------------------------------------------------------
#define NTOK   131072
#define QKVLD  288      // 192 (q) + 96 (kv) per token, bf16
#define HID    768
#define ATT_SCALE 0.17677669529663688f   // 32^-0.5

// Scratch (static device allocations — no cudaMalloc allowed)
__device__ __align__(16) __nv_bfloat16 g_xn  [(size_t)NTOK * 192]; // LN out
__device__ __align__(16) __nv_bfloat16 g_qkvb[(size_t)NTOK * QKVLD];
__device__ __align__(16) __nv_bfloat16 g_aw  [(size_t)NTOK * 192]; // attn out
__device__ __align__(16) float         g_x2  [(size_t)NTOK * 192]; // resid
__device__ __align__(16) __nv_bfloat16 g_h1  [(size_t)NTOK * HID]; // gelu(fc1)
__device__ __align__(16) __nv_bfloat16 g_h   [(size_t)NTOK * HID]; // ffn hidden
// bf16 weights: wqkv (192x288) | wproj | w1f | w2f
#define WB_WQKV  0
#define WB_WPROJ 55296
#define WB_W1F   92160
#define WB_W2F   239616
__device__ __align__(16) __nv_bfloat16 g_wb[387072];
__device__ __align__(16) float g_bqkv[288];

__device__ __forceinline__ float gelu_f(float v) {
    return 0.5f * v * (1.0f + erff(v * 0.70710678118654752440f));
}

// ---------------------------------------------------------------------------
// Weight/bias prep: concat wq|wkv into 192x288 + convert all weights to bf16
// ---------------------------------------------------------------------------
__global__ __launch_bounds__(256) void prep_kernel(
    const float* __restrict__ wq, const float* __restrict__ wkv,
    const float* __restrict__ wproj, const float* __restrict__ w1f,
    const float* __restrict__ w2f, __nv_bfloat16* __restrict__ wb,
    const float* __restrict__ bq, const float* __restrict__ bkv,
    float* __restrict__ bqkv)
{
    int i = blockIdx.x * 256 + threadIdx.x;
    if (i < 288) bqkv[i] = (i < 192) ? bq[i] : bkv[i - 192];
    if (i >= 387072) return;
    float v;
    if (i < 55296) {
        int row = i / 288, col = i - row * 288;
        v = (col < 192) ? wq[row * 192 + col] : wkv[row * 96 + col - 192];
    } else if (i < 92160) {
        v = wproj[i - 55296];
    } else if (i < 239616) {
        v = w1f[i - 92160];
    } else {
        v = w2f[i - 239616];
    }
    wb[i] = __float2bfloat16(v);
}

// ---------------------------------------------------------------------------
// LayerNorm: one warp per 192-wide row, bf16 output
// ---------------------------------------------------------------------------
__global__ __launch_bounds__(256) void ln_kernel(
    const float* __restrict__ x, const float* __restrict__ g,
    const float* __restrict__ b, __nv_bfloat16* __restrict__ out)
{
    int row  = blockIdx.x * 8 + (threadIdx.x >> 5);
    int lane = threadIdx.x & 31;
    const float* xp = x + (size_t)row * 192;
    float v[6]; float s = 0.f;
#pragma unroll
    for (int i = 0; i < 6; i++) { v[i] = xp[lane + 32*i]; s += v[i]; }
#pragma unroll
    for (int o = 16; o > 0; o >>= 1) s += __shfl_xor_sync(0xffffffffu, s, o);
    float mu = s * (1.f/192.f);
    float var = 0.f;
#pragma unroll
    for (int i = 0; i < 6; i++) { float d = v[i] - mu; var += d*d; }
#pragma unroll
    for (int o = 16; o > 0; o >>= 1) var += __shfl_xor_sync(0xffffffffu, var, o);
    float inv = rsqrtf(var * (1.f/192.f) + 1e-5f);
    __nv_bfloat16* op = out + (size_t)row * 192;
#pragma unroll
    for (int i = 0; i < 6; i++) {
        int c = lane + 32*i;
        op[c] = __float2bfloat16((v[i] - mu) * inv * g[c] + b[c]);
    }
}

// ---------------------------------------------------------------------------
// bf16 tensor-core GEMM, 3-stage cp.async pipeline + ldmatrix.
// Mainloop unrolled modulo 3 (compile-time slot indices). Loads for t+2 are
// issued BEFORE the wait (wait_group 2) — the preceding __syncthreads already
// protects the overwritten slot. REQUIRES K % 96 == 0 (K = 192 or 768 here).
//   C[m,n] = act( A[m,:] @ W[:,n] + bias[n] ) (+ res[m,n])
// BM=128, BN=64, BK=32; 256 threads = 8 warps (4m x 2n), warp tile 32x32.
// ---------------------------------------------------------------------------
__device__ __forceinline__ void cp16(uint32_t dst, const void* src, bool ok) {
    int sz = ok ? 16 : 0;
    asm volatile("cp.async.cg.shared.global [%0], [%1], 16, %2;\n"
                 :: "r"(dst), "l"(src), "r"(sz));
}
__device__ __forceinline__ void ldmx4(unsigned r[4], uint32_t addr) {
    asm volatile("ldmatrix.sync.aligned.m8n8.x4.shared.b16 {%0,%1,%2,%3}, [%4];"
                 : "=r"(r[0]), "=r"(r[1]), "=r"(r[2]), "=r"(r[3]) : "r"(addr));
}
__device__ __forceinline__ void ldmx4t(unsigned r[4], uint32_t addr) {
    asm volatile("ldmatrix.sync.aligned.m8n8.x4.trans.shared.b16 {%0,%1,%2,%3}, [%4];"
                 : "=r"(r[0]), "=r"(r[1]), "=r"(r[2]), "=r"(r[3]) : "r"(addr));
}
__device__ __forceinline__ void mma_bf16(float c[4], const unsigned a[4],
                                         unsigned b0, unsigned b1) {
    asm volatile(
        "mma.sync.aligned.m16n8k16.row.col.f32.bf16.bf16.f32 "
        "{%0,%1,%2,%3}, {%4,%5,%6,%7}, {%8,%9}, {%0,%1,%2,%3};"
        : "+f"(c[0]), "+f"(c[1]), "+f"(c[2]), "+f"(c[3])
        : "r"(a[0]), "r"(a[1]), "r"(a[2]), "r"(a[3]), "r"(b0), "r"(b1));
}

#define SA 40
#define SB 72

__global__ __launch_bounds__(256) void gemm_bf16_kernel(
    const __nv_bfloat16* __restrict__ A, int lda,
    const __nv_bfloat16* __restrict__ W, int ldw,
    const float* __restrict__ bias,
    void* __restrict__ Cc, int ldc,
    int N, int K,
    const float* __restrict__ res, int act, int out_bf16)
{
    __shared__ __align__(16) __nv_bfloat16 As[3][128 * SA];
    __shared__ __align__(16) __nv_bfloat16 Bs[3][32 * SB];
    int tid  = threadIdx.x;
    int lane = tid & 31;
    int warp = tid >> 5;
    int m0 = blockIdx.y * 128;
    int n0 = blockIdx.x * 64;
    int wm0 = (warp >> 1) * 32;
    int wn0 = (warp & 1) * 32;
    int g  = lane >> 2, cq = lane & 3;
    int ln15 = lane & 15, hi8 = (lane >> 4) << 3;

    uint32_t sAb[3], sBb[3];
#pragma unroll
    for (int s = 0; s < 3; s++) {
        sAb[s] = (uint32_t)__cvta_generic_to_shared(&As[s][0]);
        sBb[s] = (uint32_t)__cvta_generic_to_shared(&Bs[s][0]);
    }

    float acc[2][4][4];
#pragma unroll
    for (int mt = 0; mt < 2; mt++)
#pragma unroll
        for (int nt = 0; nt < 4; nt++)
#pragma unroll
            for (int r = 0; r < 4; r++) acc[mt][nt][r] = 0.f;

    int a_r0 = tid >> 2, a_c = (tid & 3) << 3;
    int b_kr = tid >> 3, b_nq = (tid & 7) << 3;
    bool b_ok = (n0 + b_nq + 8) <= N;

    int T = K >> 5;   // divisible by 3 for all uses
#define LOAD_TILE(slot, t_)                                                    \
    do {                                                                       \
        int kt_ = (t_) << 5;                                                   \
        cp16(sAb[slot] + (a_r0 * SA + a_c) * 2,                                \
             A + (size_t)(m0 + a_r0) * lda + kt_ + a_c, true);                 \
        cp16(sAb[slot] + ((a_r0 + 64) * SA + a_c) * 2,                         \
             A + (size_t)(m0 + a_r0 + 64) * lda + kt_ + a_c, true);            \
        cp16(sBb[slot] + (b_kr * SB + b_nq) * 2,                               \
             b_ok ? (const void*)(W + (size_t)(kt_ + b_kr) * ldw + n0 + b_nq)  \
                  : (const void*)W, b_ok);                                     \
        asm volatile("cp.async.commit_group;\n");                              \
    } while (0)

#define COMPUTE(slot)                                                          \
    do {                                                                       \
        uint32_t ab = sAb[slot], bb = sBb[slot];                               \
        _Pragma("unroll")                                                      \
        for (int kb = 0; kb < 32; kb += 16) {                                  \
            unsigned af[2][4], bf[2][4];                                       \
            _Pragma("unroll")                                                  \
            for (int mt = 0; mt < 2; mt++)                                     \
                ldmx4(af[mt], ab + ((wm0 + mt*16 + ln15) * SA + kb + hi8) * 2);\
            _Pragma("unroll")                                                  \
            for (int np = 0; np < 2; np++)                                     \
                ldmx4t(bf[np], bb + ((kb + ln15) * SB + wn0 + np*16 + hi8) * 2);\
            _Pragma("unroll")                                                  \
            for (int mt = 0; mt < 2; mt++)                                     \
                _Pragma("unroll")                                              \
                for (int nt = 0; nt < 4; nt++)                                 \
                    mma_bf16(acc[mt][nt], af[mt],                              \
                             bf[nt >> 1][(nt & 1) * 2],                        \
                             bf[nt >> 1][(nt & 1) * 2 + 1]);                   \
        }                                                                      \
    } while (0)

#define STEP(slot, nslot, t_)                                                  \
    do {                                                                       \
        __syncthreads();                                                       \
        if ((t_) + 2 < T) {                                                    \
            LOAD_TILE(nslot, (t_) + 2);                                        \
            asm volatile("cp.async.wait_group 2;\n");                          \
        } else if ((t_) + 1 < T) {                                             \
            asm volatile("cp.async.wait_group 1;\n");                          \
        } else {                                                               \
            asm volatile("cp.async.wait_group 0;\n");                          \
        }                                                                      \
        __syncthreads();                                                       \
        COMPUTE(slot);                                                         \
    } while (0)

    LOAD_TILE(0, 0);
    LOAD_TILE(1, 1);
    for (int t = 0; t < T; t += 3) {
        STEP(0, 2, t);
        STEP(1, 0, t + 1);
        STEP(2, 1, t + 2);
    }
#undef STEP
#undef COMPUTE
#undef LOAD_TILE

    // -------- epilogue: bias (+gelu) (+residual), fp32 or bf16 out --------
#pragma unroll
    for (int mt = 0; mt < 2; mt++) {
        int row0 = m0 + wm0 + mt * 16 + g;
#pragma unroll
        for (int nt = 0; nt < 4; nt++) {
            int col = n0 + wn0 + nt * 8 + cq * 2;
            if (col < N) {
                float b0 = bias[col], b1 = bias[col + 1];
#pragma unroll
                for (int hh = 0; hh < 2; hh++) {
                    int row = row0 + 8 * hh;
                    float v0 = acc[mt][nt][hh * 2 + 0] + b0;
                    float v1 = acc[mt][nt][hh * 2 + 1] + b1;
                    if (act) { v0 = gelu_f(v0); v1 = gelu_f(v1); }
                    if (res) {
                        float2 rr = *(const float2*)&res[(size_t)row * ldc + col];
                        v0 += rr.x; v1 += rr.y;
                    }
                    if (out_bf16) {
                        *(__nv_bfloat162*)&((__nv_bfloat16*)Cc)[(size_t)row * ldc + col] =
                            __float22bfloat162_rn(make_float2(v0, v1));
                    } else {
                        *(float2*)&((float*)Cc)[(size_t)row * ldc + col] =
                            make_float2(v0, v1);
                    }
                }
            }
        }
    }
}

// ---------------------------------------------------------------------------
// Windowed PSA attention.  One block per 8x8 window (2048 windows).
// 384 threads = 64 q-tokens x 6 heads; softmax over 16 kv in registers.
// Gather: one uint4 per thread per array; compute on float4 smem loads.
// ---------------------------------------------------------------------------
__global__ __launch_bounds__(384) void attn_kernel(
    const __nv_bfloat16* __restrict__ qkv,
    const float* __restrict__ bias_table,
    __nv_bfloat16* __restrict__ aw)
{
    __shared__ float ks[16][192];
    __shared__ float vs[16][192];
    __shared__ float bt[296];
    int w  = blockIdx.x;
    int b  = w >> 10;
    int wi = w & 1023;
    int wy = wi >> 5, wx = wi & 31;
    int gbase = b*65536 + wy*2048 + wx*8;
    int tid = threadIdx.x;

    for (int i = tid; i < 294; i += 384) bt[i] = bias_table[i];
    {
        int kt = tid / 24;
        int f0 = (tid - kt * 24) * 8;
        int s0 = f0 / 96;
        int s1 = (f0 / 48) & 1;
        int c  = f0 % 48;
        int p0 = kt >> 2, p1 = kt & 3;
        int g  = gbase + (p0*2 + s0)*256 + (p1*2 + s1);
        const __nv_bfloat16* row = qkv + (size_t)g*QKVLD + 192;
        uint4 kraw = *(const uint4*)(row + c);
        uint4 vraw = *(const uint4*)(row + 48 + c);
        const __nv_bfloat162* kp = (const __nv_bfloat162*)&kraw;
        const __nv_bfloat162* vp = (const __nv_bfloat162*)&vraw;
        float2 t0 = __bfloat1622float2(kp[0]), t1 = __bfloat1622float2(kp[1]);
        float2 t2 = __bfloat1622float2(kp[2]), t3 = __bfloat1622float2(kp[3]);
        *(float4*)&ks[kt][f0]     = make_float4(t0.x, t0.y, t1.x, t1.y);
        *(float4*)&ks[kt][f0 + 4] = make_float4(t2.x, t2.y, t3.x, t3.y);
        t0 = __bfloat1622float2(vp[0]); t1 = __bfloat1622float2(vp[1]);
        t2 = __bfloat1622float2(vp[2]); t3 = __bfloat1622float2(vp[3]);
        *(float4*)&vs[kt][f0]     = make_float4(t0.x, t0.y, t1.x, t1.y);
        *(float4*)&vs[kt][f0 + 4] = make_float4(t2.x, t2.y, t3.x, t3.y);
    }
    __syncthreads();

    int h  = tid / 64;
    int qt = tid - h*64;
    int qi = qt >> 3, qj = qt & 7;
    int g  = gbase + qi*256 + qj;
    const __nv_bfloat16* qp = qkv + (size_t)g*QKVLD + h*32;
    float4 q4[8];
#pragma unroll
    for (int d = 0; d < 4; d++) {
        uint4 raw = *(const uint4*)(qp + d*8);
        const __nv_bfloat162* p2 = (const __nv_bfloat162*)&raw;
        float2 a0 = __bfloat1622float2(p2[0]);
        float2 a1 = __bfloat1622float2(p2[1]);
        float2 a2 = __bfloat1622float2(p2[2]);
        float2 a3 = __bfloat1622float2(p2[3]);
        q4[d*2]   = make_float4(a0.x*ATT_SCALE, a0.y*ATT_SCALE,
                                a1.x*ATT_SCALE, a1.y*ATT_SCALE);
        q4[d*2+1] = make_float4(a2.x*ATT_SCALE, a2.y*ATT_SCALE,
                                a3.x*ATT_SCALE, a3.y*ATT_SCALE);
    }
    float sc[16]; float mx = -1e30f;
    int rq0 = (qi >> 1) + 3, rq1 = (qj >> 1) + 3;
#pragma unroll
    for (int kt = 0; kt < 16; kt++) {
        const float4* kr = (const float4*)&ks[kt][h*32];
        float s = 0.f;
#pragma unroll
        for (int j = 0; j < 8; j++) {
            float4 kv4 = kr[j];
            s += q4[j].x*kv4.x + q4[j].y*kv4.y + q4[j].z*kv4.z + q4[j].w*kv4.w;
        }
        int rel = (rq0 - (kt >> 2))*7 + rq1 - (kt & 3);
        s += bt[rel*6 + h];
        sc[kt] = s;
        mx = fmaxf(mx, s);
    }
    float sum = 0.f;
#pragma unroll
    for (int kt = 0; kt < 16; kt++) { sc[kt] = __expf(sc[kt] - mx); sum += sc[kt]; }
    float inv = 1.f / sum;
    float4 o4[8];
#pragma unroll
    for (int j = 0; j < 8; j++) o4[j] = make_float4(0.f, 0.f, 0.f, 0.f);
#pragma unroll
    for (int kt = 0; kt < 16; kt++) {
        float a = sc[kt]*inv;
        const float4* vr = (const float4*)&vs[kt][h*32];
#pragma unroll
        for (int j = 0; j < 8; j++) {
            float4 vv = vr[j];
            o4[j].x += a*vv.x; o4[j].y += a*vv.y;
            o4[j].z += a*vv.z; o4[j].w += a*vv.w;
        }
    }
    __nv_bfloat16* op = aw + (size_t)g*192 + h*32;
#pragma unroll
    for (int j = 0; j < 4; j++) {
        uint4 o;
        __nv_bfloat162* o2 = (__nv_bfloat162*)&o;
        o2[0] = __float22bfloat162_rn(make_float2(o4[j*2].x,   o4[j*2].y));
        o2[1] = __float22bfloat162_rn(make_float2(o4[j*2].z,   o4[j*2].w));
        o2[2] = __float22bfloat162_rn(make_float2(o4[j*2+1].x, o4[j*2+1].y));
        o2[3] = __float22bfloat162_rn(make_float2(o4[j*2+1].z, o4[j*2+1].w));
        *(uint4*)(op + j*8) = o;
    }
}

// ---------------------------------------------------------------------------
// Depthwise 5x5 conv + GELU + residual:  out = h1 + gelu(conv(h1) + dwb)
// 2 x-adjacent tokens x 8 channels per thread: the shared 5x6 column window
// (30 LDG.128) feeds both tokens' 2x25 taps. Packed bf16 __hfma2 math.
// Block: 256 threads = 16 pairs x 16 channel-octets -> 32 tokens (same row).
// ---------------------------------------------------------------------------
__global__ __launch_bounds__(256) void dwconv_kernel(
    const __nv_bfloat16* __restrict__ h1, const float* __restrict__ wk,
    const float* __restrict__ wb, __nv_bfloat16* __restrict__ out)
{
    __shared__ __align__(16) uint32_t ws2[25][64];  // bf16x2 per channel pair
    __shared__ float bs[128];
    int cb  = blockIdx.y * 128;
    int tid = threadIdx.x;
    for (int i = tid; i < 1600; i += 256) {
        int k = i >> 6, pp = i & 63;
        __nv_bfloat162 pk = __floats2bfloat162_rn(
            wk[(size_t)(cb + 2*pp)     * 25 + k],
            wk[(size_t)(cb + 2*pp + 1) * 25 + k]);
        ws2[k][pp] = *reinterpret_cast<uint32_t*>(&pk);
    }
    if (tid < 128) bs[tid] = wb[cb + tid];
    __syncthreads();

    int tl = tid >> 4;                    // pair index (0..15)
    int oc = tid & 15;                    // channel octet
    int token0 = blockIdx.x * 32 + tl * 2;
    int b = token0 >> 16;
    int p = token0 & 65535;
    int y = p >> 8, x0 = p & 255;         // token1 is x0+1, same row
    int ch = cb + oc * 8;
    const size_t rowbase = (size_t)(b * 65536 + y * 256);

    __nv_bfloat162 z = __float2bfloat162_rn(0.f);
    __nv_bfloat162 acc0[4], acc1[4];
#pragma unroll
    for (int j = 0; j < 4; j++) { acc0[j] = z; acc1[j] = z; }
    uint4 cen0 = make_uint4(0u,0u,0u,0u), cen1 = make_uint4(0u,0u,0u,0u);

#pragma unroll
    for (int dy = 0; dy < 5; dy++) {
        int yy = y + dy - 2;
        bool yok = (unsigned)yy < 256u;
        size_t rb = (size_t)(b * 65536 + yy * 256);
        uint4 col[6];
#pragma unroll
        for (int jx = 0; jx < 6; jx++) {
            int xc = x0 + jx - 2;
            uint4 v = make_uint4(0u, 0u, 0u, 0u);
            if (yok && (unsigned)xc < 256u)
                v = *(const uint4*)&h1[(rb + xc) * HID + ch];
            col[jx] = v;
        }
        if (dy == 2) { cen0 = col[2]; cen1 = col[3]; }
#pragma unroll
        for (int jx = 0; jx < 6; jx++) {
            const __nv_bfloat162* vp = reinterpret_cast<const __nv_bfloat162*>(&col[jx]);
            if (jx < 5) {                 // token0 tap jx
                uint4 wv = *(const uint4*)&ws2[dy*5 + jx][oc*4];
                const __nv_bfloat162* wp = reinterpret_cast<const __nv_bfloat162*>(&wv);
#pragma unroll
                for (int j = 0; j < 4; j++)
                    acc0[j] = __hfma2(vp[j], wp[j], acc0[j]);
            }
            if (jx >= 1) {                // token1 tap jx-1
                uint4 wv = *(const uint4*)&ws2[dy*5 + jx - 1][oc*4];
                const __nv_bfloat162* wp = reinterpret_cast<const __nv_bfloat162*>(&wv);
#pragma unroll
                for (int j = 0; j < 4; j++)
                    acc1[j] = __hfma2(vp[j], wp[j], acc1[j]);
            }
        }
    }

    // epilogue for both tokens
    const __nv_bfloat162* c0 = reinterpret_cast<const __nv_bfloat162*>(&cen0);
    const __nv_bfloat162* c1 = reinterpret_cast<const __nv_bfloat162*>(&cen1);
    uint4 o0, o1;
    __nv_bfloat162* p0 = reinterpret_cast<__nv_bfloat162*>(&o0);
    __nv_bfloat162* p1 = reinterpret_cast<__nv_bfloat162*>(&o1);
#pragma unroll
    for (int j = 0; j < 4; j++) {
        float b0 = bs[oc*8 + 2*j], b1 = bs[oc*8 + 2*j + 1];
        float2 a = __bfloat1622float2(acc0[j]);
        float2 c = __bfloat1622float2(c0[j]);
        p0[j] = __float22bfloat162_rn(make_float2(c.x + gelu_f(a.x + b0),
                                                  c.y + gelu_f(a.y + b1)));
        a = __bfloat1622float2(acc1[j]);
        c = __bfloat1622float2(c1[j]);
        p1[j] = __float22bfloat162_rn(make_float2(c.x + gelu_f(a.x + b0),
                                                  c.y + gelu_f(a.y + b1)));
    }
    *(uint4*)&out[(rowbase + x0)     * HID + ch] = o0;
    *(uint4*)&out[(rowbase + x0 + 1) * HID + ch] = o1;
}

// ---------------------------------------------------------------------------
// Launch sequence (graph-capturable: kernel launches only)
// ---------------------------------------------------------------------------
extern "C" void kernel_launch(void* const* d_in, const int* in_sizes, int n_in,
                              void* d_out, int out_size)
{
    const float* x    = (const float*)d_in[0];
    const float* g1   = (const float*)d_in[1];
    const float* be1  = (const float*)d_in[2];
    const float* wq   = (const float*)d_in[3];
    const float* bq   = (const float*)d_in[4];
    const float* wkv  = (const float*)d_in[5];
    const float* bkv  = (const float*)d_in[6];
    const float* btab = (const float*)d_in[7];
    const float* wproj= (const float*)d_in[8];
    const float* bproj= (const float*)d_in[9];
    const float* g2   = (const float*)d_in[10];
    const float* be2  = (const float*)d_in[11];
    const float* w1f  = (const float*)d_in[12];
    const float* b1f  = (const float*)d_in[13];
    const float* dwk  = (const float*)d_in[14];
    const float* dwb  = (const float*)d_in[15];
    const float* w2f  = (const float*)d_in[16];
    const float* b2f  = (const float*)d_in[17];
    float* out = (float*)d_out;

    __nv_bfloat16 *xn, *qkvb, *aw, *h1, *h, *wb;
    float *x2, *bqkv;
    cudaGetSymbolAddress((void**)&xn,   g_xn);
    cudaGetSymbolAddress((void**)&qkvb, g_qkvb);
    cudaGetSymbolAddress((void**)&aw,   g_aw);
    cudaGetSymbolAddress((void**)&x2,   g_x2);
    cudaGetSymbolAddress((void**)&h1,   g_h1);
    cudaGetSymbolAddress((void**)&h,    g_h);
    cudaGetSymbolAddress((void**)&wb,   g_wb);
    cudaGetSymbolAddress((void**)&bqkv, g_bqkv);

    // 0. Weight/bias prep (bf16, QKV concat)
    prep_kernel<<<(387072 + 255)/256, 256>>>(wq, wkv, wproj, w1f, w2f, wb,
                                             bq, bkv, bqkv);

    // 1. LN1 -> xn (bf16)
    ln_kernel<<<NTOK/8, 256>>>(x, g1, be1, xn);
    // 2. QKV = xn @ wqkv + bqkv  (bf16, ldc=288; N=288 -> 5 n-blocks)
    gemm_bf16_kernel<<<dim3(5, NTOK/128), 256>>>(xn, 192, wb + WB_WQKV, 288, bqkv,
                                                 qkvb, QKVLD, 288, 192,
                                                 nullptr, 0, 1);
    // 3. Window attention -> aw (bf16, token order)
    attn_kernel<<<2048, 384>>>(qkvb, btab, aw);
    // 4. x2 = aw @ wproj + bproj + x  (fp32)
    gemm_bf16_kernel<<<dim3(3, NTOK/128), 256>>>(aw, 192, wb + WB_WPROJ, 192, bproj,
                                                 x2, 192, 192, 192,
                                                 x, 0, 0);
    // 5. LN2 -> xn (bf16)
    ln_kernel<<<NTOK/8, 256>>>(x2, g2, be2, xn);
    // 6. h1 = gelu(xn @ w1f + b1f)  (bf16)
    gemm_bf16_kernel<<<dim3(12, NTOK/128), 256>>>(xn, 192, wb + WB_W1F, HID, b1f,
                                                  h1, HID, HID, 192,
                                                  nullptr, 1, 1);
    // 7. h = h1 + gelu(dwconv(h1) + dwb)  (bf16, 2 tokens/thread)
    dwconv_kernel<<<dim3(NTOK/32, 6), 256>>>(h1, dwk, dwb, h);
    // 8. out = h @ w2f + b2f + x2  (fp32)
    gemm_bf16_kernel<<<dim3(3, NTOK/128), 256>>>(h, HID, wb + WB_W2F, 192, b2f,
                                                 out, 192, 192, HID,
                                                 x2, 0, 0);
}

// round 14
// speedup vs baseline: 1.7160x; 1.0012x over previous
#include <cuda_runtime.h>
#include <cuda_bf16.h>
#include <cstdint>
#include <math.h>

// ---------------------------------------------------------------------------
// Problem constants
//   B=2, H=W=256, C=192, HEADS=6, HEAD_DIM=32, WS=8, PW=4, HIDDEN=768
//   NTOK = B*H*W = 131072 tokens
// ---------------------------------------------------------------------------
#define NTOK   131072
#define QKVLD  288      // 192 (q) + 96 (kv) per token, bf16
#define HID    768
#define ATT_SCALE 0.17677669529663688f   // 32^-0.5

// Scratch (static device allocations — no cudaMalloc allowed)
__device__ __align__(16) __nv_bfloat16 g_xn  [(size_t)NTOK * 192]; // LN out
__device__ __align__(16) __nv_bfloat16 g_qkvb[(size_t)NTOK * QKVLD];
__device__ __align__(16) __nv_bfloat16 g_aw  [(size_t)NTOK * 192]; // attn out
__device__ __align__(16) float         g_x2  [(size_t)NTOK * 192]; // resid
__device__ __align__(16) __nv_bfloat16 g_h1  [(size_t)NTOK * HID]; // gelu(fc1)
__device__ __align__(16) __nv_bfloat16 g_h   [(size_t)NTOK * HID]; // ffn hidden
// bf16 weights: wqkv (192x288) | wproj | w1f | w2f
#define WB_WQKV  0
#define WB_WPROJ 55296
#define WB_W1F   92160
#define WB_W2F   239616
__device__ __align__(16) __nv_bfloat16 g_wb[387072];
__device__ __align__(16) float g_bqkv[288];

__device__ __forceinline__ float gelu_f(float v) {
    return 0.5f * v * (1.0f + erff(v * 0.70710678118654752440f));
}

// ---------------------------------------------------------------------------
// Weight/bias prep: concat wq|wkv into 192x288 + convert all weights to bf16
// ---------------------------------------------------------------------------
__global__ __launch_bounds__(256) void prep_kernel(
    const float* __restrict__ wq, const float* __restrict__ wkv,
    const float* __restrict__ wproj, const float* __restrict__ w1f,
    const float* __restrict__ w2f, __nv_bfloat16* __restrict__ wb,
    const float* __restrict__ bq, const float* __restrict__ bkv,
    float* __restrict__ bqkv)
{
    int i = blockIdx.x * 256 + threadIdx.x;
    if (i < 288) bqkv[i] = (i < 192) ? bq[i] : bkv[i - 192];
    if (i >= 387072) return;
    float v;
    if (i < 55296) {
        int row = i / 288, col = i - row * 288;
        v = (col < 192) ? wq[row * 192 + col] : wkv[row * 96 + col - 192];
    } else if (i < 92160) {
        v = wproj[i - 55296];
    } else if (i < 239616) {
        v = w1f[i - 92160];
    } else {
        v = w2f[i - 239616];
    }
    wb[i] = __float2bfloat16(v);
}

// ---------------------------------------------------------------------------
// LayerNorm: one warp per 192-wide row, bf16 output
// ---------------------------------------------------------------------------
__global__ __launch_bounds__(256) void ln_kernel(
    const float* __restrict__ x, const float* __restrict__ g,
    const float* __restrict__ b, __nv_bfloat16* __restrict__ out)
{
    int row  = blockIdx.x * 8 + (threadIdx.x >> 5);
    int lane = threadIdx.x & 31;
    const float* xp = x + (size_t)row * 192;
    float v[6]; float s = 0.f;
#pragma unroll
    for (int i = 0; i < 6; i++) { v[i] = xp[lane + 32*i]; s += v[i]; }
#pragma unroll
    for (int o = 16; o > 0; o >>= 1) s += __shfl_xor_sync(0xffffffffu, s, o);
    float mu = s * (1.f/192.f);
    float var = 0.f;
#pragma unroll
    for (int i = 0; i < 6; i++) { float d = v[i] - mu; var += d*d; }
#pragma unroll
    for (int o = 16; o > 0; o >>= 1) var += __shfl_xor_sync(0xffffffffu, var, o);
    float inv = rsqrtf(var * (1.f/192.f) + 1e-5f);
    __nv_bfloat16* op = out + (size_t)row * 192;
#pragma unroll
    for (int i = 0; i < 6; i++) {
        int c = lane + 32*i;
        op[c] = __float2bfloat16((v[i] - mu) * inv * g[c] + b[c]);
    }
}

// ---------------------------------------------------------------------------
// bf16 tensor-core GEMM, 3-stage cp.async pipeline + ldmatrix.
// Templated on BN (64 or 128). Warp tile 32 x BN/2. Mainloop unrolled
// modulo 3 (compile-time slot indices); t+2 loads issued before the wait.
// REQUIRES K % 96 == 0 (K = 192 or 768 here). Dynamic smem.
// ---------------------------------------------------------------------------
__device__ __forceinline__ void cp16(uint32_t dst, const void* src, bool ok) {
    int sz = ok ? 16 : 0;
    asm volatile("cp.async.cg.shared.global [%0], [%1], 16, %2;\n"
                 :: "r"(dst), "l"(src), "r"(sz));
}
__device__ __forceinline__ void ldmx4(unsigned r[4], uint32_t addr) {
    asm volatile("ldmatrix.sync.aligned.m8n8.x4.shared.b16 {%0,%1,%2,%3}, [%4];"
                 : "=r"(r[0]), "=r"(r[1]), "=r"(r[2]), "=r"(r[3]) : "r"(addr));
}
__device__ __forceinline__ void ldmx4t(unsigned r[4], uint32_t addr) {
    asm volatile("ldmatrix.sync.aligned.m8n8.x4.trans.shared.b16 {%0,%1,%2,%3}, [%4];"
                 : "=r"(r[0]), "=r"(r[1]), "=r"(r[2]), "=r"(r[3]) : "r"(addr));
}
__device__ __forceinline__ void mma_bf16(float c[4], const unsigned a[4],
                                         unsigned b0, unsigned b1) {
    asm volatile(
        "mma.sync.aligned.m16n8k16.row.col.f32.bf16.bf16.f32 "
        "{%0,%1,%2,%3}, {%4,%5,%6,%7}, {%8,%9}, {%0,%1,%2,%3};"
        : "+f"(c[0]), "+f"(c[1]), "+f"(c[2]), "+f"(c[3])
        : "r"(a[0]), "r"(a[1]), "r"(a[2]), "r"(a[3]), "r"(b0), "r"(b1));
}

#define SA 40

template<int BN>
__global__ __launch_bounds__(256) void gemm_bf16_kernel(
    const __nv_bfloat16* __restrict__ A, int lda,
    const __nv_bfloat16* __restrict__ W, int ldw,
    const float* __restrict__ bias,
    void* __restrict__ Cc, int ldc,
    int N, int K,
    const float* __restrict__ res, int act, int out_bf16)
{
    constexpr int SBT = BN + 8;          // bf16 stride of B tile rows
    constexpr int NT  = BN / 16;         // n-fragments per warp
    constexpr int NP  = BN / 32;         // ldmx4t count per warp per k16
    constexpr int BL  = BN / 64;         // B cp16 loads per thread
    constexpr int CPR = BN / 8;          // 16B chunks per B row
    extern __shared__ __align__(16) __nv_bfloat16 smem[];
    __nv_bfloat16* Asm = smem;                    // 3 x 128*SA
    __nv_bfloat16* Bsm = smem + 3 * 128 * SA;     // 3 x 32*SBT
    int tid  = threadIdx.x;
    int lane = tid & 31;
    int warp = tid >> 5;
    int m0 = blockIdx.y * 128;
    int n0 = blockIdx.x * BN;
    int wm0 = (warp >> 1) * 32;
    int wn0 = (warp & 1) * (BN / 2);
    int g  = lane >> 2, cq = lane & 3;
    int ln15 = lane & 15, hi8 = (lane >> 4) << 3;

    uint32_t sAb[3], sBb[3];
#pragma unroll
    for (int s = 0; s < 3; s++) {
        sAb[s] = (uint32_t)__cvta_generic_to_shared(Asm + s * 128 * SA);
        sBb[s] = (uint32_t)__cvta_generic_to_shared(Bsm + s * 32 * SBT);
    }

    float acc[2][NT][4];
#pragma unroll
    for (int mt = 0; mt < 2; mt++)
#pragma unroll
        for (int nt = 0; nt < NT; nt++)
#pragma unroll
            for (int r = 0; r < 4; r++) acc[mt][nt][r] = 0.f;

    int a_r0 = tid >> 2, a_c = (tid & 3) << 3;
    int b_kr[BL], b_nq[BL]; bool b_okk[BL];
#pragma unroll
    for (int i = 0; i < BL; i++) {
        int ch = tid + i * 256;
        b_kr[i] = ch / CPR;
        b_nq[i] = (ch % CPR) * 8;
        b_okk[i] = (n0 + b_nq[i] + 8) <= N;
    }

    int T = K >> 5;   // divisible by 3 for all uses
#define LOAD_TILE(slot, t_)                                                    \
    do {                                                                       \
        int kt_ = (t_) << 5;                                                   \
        cp16(sAb[slot] + (a_r0 * SA + a_c) * 2,                                \
             A + (size_t)(m0 + a_r0) * lda + kt_ + a_c, true);                 \
        cp16(sAb[slot] + ((a_r0 + 64) * SA + a_c) * 2,                         \
             A + (size_t)(m0 + a_r0 + 64) * lda + kt_ + a_c, true);            \
        _Pragma("unroll")                                                      \
        for (int i_ = 0; i_ < BL; i_++)                                        \
            cp16(sBb[slot] + (b_kr[i_] * SBT + b_nq[i_]) * 2,                  \
                 b_okk[i_] ? (const void*)(W + (size_t)(kt_ + b_kr[i_]) * ldw  \
                                           + n0 + b_nq[i_])                    \
                           : (const void*)W, b_okk[i_]);                       \
        asm volatile("cp.async.commit_group;\n");                              \
    } while (0)

#define COMPUTE(slot)                                                          \
    do {                                                                       \
        uint32_t ab = sAb[slot], bb = sBb[slot];                               \
        _Pragma("unroll")                                                      \
        for (int kb = 0; kb < 32; kb += 16) {                                  \
            unsigned af[2][4], bf[NP][4];                                      \
            _Pragma("unroll")                                                  \
            for (int mt = 0; mt < 2; mt++)                                     \
                ldmx4(af[mt], ab + ((wm0 + mt*16 + ln15) * SA + kb + hi8) * 2);\
            _Pragma("unroll")                                                  \
            for (int np = 0; np < NP; np++)                                    \
                ldmx4t(bf[np], bb + ((kb + ln15) * SBT + wn0 + np*16 + hi8) * 2);\
            _Pragma("unroll")                                                  \
            for (int mt = 0; mt < 2; mt++)                                     \
                _Pragma("unroll")                                              \
                for (int nt = 0; nt < NT; nt++)                                \
                    mma_bf16(acc[mt][nt], af[mt],                              \
                             bf[nt >> 1][(nt & 1) * 2],                        \
                             bf[nt >> 1][(nt & 1) * 2 + 1]);                   \
        }                                                                      \
    } while (0)

#define STEP(slot, nslot, t_)                                                  \
    do {                                                                       \
        __syncthreads();                                                       \
        if ((t_) + 2 < T) {                                                    \
            LOAD_TILE(nslot, (t_) + 2);                                        \
            asm volatile("cp.async.wait_group 2;\n");                          \
        } else if ((t_) + 1 < T) {                                             \
            asm volatile("cp.async.wait_group 1;\n");                          \
        } else {                                                               \
            asm volatile("cp.async.wait_group 0;\n");                          \
        }                                                                      \
        __syncthreads();                                                       \
        COMPUTE(slot);                                                         \
    } while (0)

    LOAD_TILE(0, 0);
    LOAD_TILE(1, 1);
    for (int t = 0; t < T; t += 3) {
        STEP(0, 2, t);
        STEP(1, 0, t + 1);
        STEP(2, 1, t + 2);
    }
#undef STEP
#undef COMPUTE
#undef LOAD_TILE

    // -------- epilogue: bias (+gelu) (+residual), fp32 or bf16 out --------
#pragma unroll
    for (int mt = 0; mt < 2; mt++) {
        int row0 = m0 + wm0 + mt * 16 + g;
#pragma unroll
        for (int nt = 0; nt < NT; nt++) {
            int col = n0 + wn0 + nt * 8 + cq * 2;
            if (col < N) {
                float b0 = bias[col], b1 = bias[col + 1];
#pragma unroll
                for (int hh = 0; hh < 2; hh++) {
                    int row = row0 + 8 * hh;
                    float v0 = acc[mt][nt][hh * 2 + 0] + b0;
                    float v1 = acc[mt][nt][hh * 2 + 1] + b1;
                    if (act) { v0 = gelu_f(v0); v1 = gelu_f(v1); }
                    if (res) {
                        float2 rr = *(const float2*)&res[(size_t)row * ldc + col];
                        v0 += rr.x; v1 += rr.y;
                    }
                    if (out_bf16) {
                        *(__nv_bfloat162*)&((__nv_bfloat16*)Cc)[(size_t)row * ldc + col] =
                            __float22bfloat162_rn(make_float2(v0, v1));
                    } else {
                        *(float2*)&((float*)Cc)[(size_t)row * ldc + col] =
                            make_float2(v0, v1);
                    }
                }
            }
        }
    }
}

// ---------------------------------------------------------------------------
// Windowed PSA attention.  One block per 8x8 window (2048 windows).
// 384 threads = 64 q-tokens x 6 heads; softmax over 16 kv in registers.
// ---------------------------------------------------------------------------
__global__ __launch_bounds__(384) void attn_kernel(
    const __nv_bfloat16* __restrict__ qkv,
    const float* __restrict__ bias_table,
    __nv_bfloat16* __restrict__ aw)
{
    __shared__ float ks[16][192];
    __shared__ float vs[16][192];
    __shared__ float bt[296];
    int w  = blockIdx.x;
    int b  = w >> 10;
    int wi = w & 1023;
    int wy = wi >> 5, wx = wi & 31;
    int gbase = b*65536 + wy*2048 + wx*8;
    int tid = threadIdx.x;

    for (int i = tid; i < 294; i += 384) bt[i] = bias_table[i];
    {
        int kt = tid / 24;
        int f0 = (tid - kt * 24) * 8;
        int s0 = f0 / 96;
        int s1 = (f0 / 48) & 1;
        int c  = f0 % 48;
        int p0 = kt >> 2, p1 = kt & 3;
        int g  = gbase + (p0*2 + s0)*256 + (p1*2 + s1);
        const __nv_bfloat16* row = qkv + (size_t)g*QKVLD + 192;
        uint4 kraw = *(const uint4*)(row + c);
        uint4 vraw = *(const uint4*)(row + 48 + c);
        const __nv_bfloat162* kp = (const __nv_bfloat162*)&kraw;
        const __nv_bfloat162* vp = (const __nv_bfloat162*)&vraw;
        float2 t0 = __bfloat1622float2(kp[0]), t1 = __bfloat1622float2(kp[1]);
        float2 t2 = __bfloat1622float2(kp[2]), t3 = __bfloat1622float2(kp[3]);
        *(float4*)&ks[kt][f0]     = make_float4(t0.x, t0.y, t1.x, t1.y);
        *(float4*)&ks[kt][f0 + 4] = make_float4(t2.x, t2.y, t3.x, t3.y);
        t0 = __bfloat1622float2(vp[0]); t1 = __bfloat1622float2(vp[1]);
        t2 = __bfloat1622float2(vp[2]); t3 = __bfloat1622float2(vp[3]);
        *(float4*)&vs[kt][f0]     = make_float4(t0.x, t0.y, t1.x, t1.y);
        *(float4*)&vs[kt][f0 + 4] = make_float4(t2.x, t2.y, t3.x, t3.y);
    }
    __syncthreads();

    int h  = tid / 64;
    int qt = tid - h*64;
    int qi = qt >> 3, qj = qt & 7;
    int g  = gbase + qi*256 + qj;
    const __nv_bfloat16* qp = qkv + (size_t)g*QKVLD + h*32;
    float4 q4[8];
#pragma unroll
    for (int d = 0; d < 4; d++) {
        uint4 raw = *(const uint4*)(qp + d*8);
        const __nv_bfloat162* p2 = (const __nv_bfloat162*)&raw;
        float2 a0 = __bfloat1622float2(p2[0]);
        float2 a1 = __bfloat1622float2(p2[1]);
        float2 a2 = __bfloat1622float2(p2[2]);
        float2 a3 = __bfloat1622float2(p2[3]);
        q4[d*2]   = make_float4(a0.x*ATT_SCALE, a0.y*ATT_SCALE,
                                a1.x*ATT_SCALE, a1.y*ATT_SCALE);
        q4[d*2+1] = make_float4(a2.x*ATT_SCALE, a2.y*ATT_SCALE,
                                a3.x*ATT_SCALE, a3.y*ATT_SCALE);
    }
    float sc[16]; float mx = -1e30f;
    int rq0 = (qi >> 1) + 3, rq1 = (qj >> 1) + 3;
#pragma unroll
    for (int kt = 0; kt < 16; kt++) {
        const float4* kr = (const float4*)&ks[kt][h*32];
        float s = 0.f;
#pragma unroll
        for (int j = 0; j < 8; j++) {
            float4 kv4 = kr[j];
            s += q4[j].x*kv4.x + q4[j].y*kv4.y + q4[j].z*kv4.z + q4[j].w*kv4.w;
        }
        int rel = (rq0 - (kt >> 2))*7 + rq1 - (kt & 3);
        s += bt[rel*6 + h];
        sc[kt] = s;
        mx = fmaxf(mx, s);
    }
    float sum = 0.f;
#pragma unroll
    for (int kt = 0; kt < 16; kt++) { sc[kt] = __expf(sc[kt] - mx); sum += sc[kt]; }
    float inv = 1.f / sum;
    float4 o4[8];
#pragma unroll
    for (int j = 0; j < 8; j++) o4[j] = make_float4(0.f, 0.f, 0.f, 0.f);
#pragma unroll
    for (int kt = 0; kt < 16; kt++) {
        float a = sc[kt]*inv;
        const float4* vr = (const float4*)&vs[kt][h*32];
#pragma unroll
        for (int j = 0; j < 8; j++) {
            float4 vv = vr[j];
            o4[j].x += a*vv.x; o4[j].y += a*vv.y;
            o4[j].z += a*vv.z; o4[j].w += a*vv.w;
        }
    }
    __nv_bfloat16* op = aw + (size_t)g*192 + h*32;
#pragma unroll
    for (int j = 0; j < 4; j++) {
        uint4 o;
        __nv_bfloat162* o2 = (__nv_bfloat162*)&o;
        o2[0] = __float22bfloat162_rn(make_float2(o4[j*2].x,   o4[j*2].y));
        o2[1] = __float22bfloat162_rn(make_float2(o4[j*2].z,   o4[j*2].w));
        o2[2] = __float22bfloat162_rn(make_float2(o4[j*2+1].x, o4[j*2+1].y));
        o2[3] = __float22bfloat162_rn(make_float2(o4[j*2+1].z, o4[j*2+1].w));
        *(uint4*)(op + j*8) = o;
    }
}

// ---------------------------------------------------------------------------
// Depthwise 5x5 conv + GELU + residual:  out = h1 + gelu(conv(h1) + dwb)
// 4 x-adjacent tokens x 8 channels per thread: shared 5x8 column window
// (40 LDG.128) feeds all 4 tokens' taps (10 LDG/token). Packed __hfma2.
// Block: 256 threads = 16 quads x 16 channel-octets -> 64 tokens (same row).
// ---------------------------------------------------------------------------
__global__ __launch_bounds__(256) void dwconv_kernel(
    const __nv_bfloat16* __restrict__ h1, const float* __restrict__ wk,
    const float* __restrict__ wb, __nv_bfloat16* __restrict__ out)
{
    __shared__ __align__(16) uint32_t ws2[25][64];  // bf16x2 per channel pair
    __shared__ float bs[128];
    int cb  = blockIdx.y * 128;
    int tid = threadIdx.x;
    for (int i = tid; i < 1600; i += 256) {
        int k = i >> 6, pp = i & 63;
        __nv_bfloat162 pk = __floats2bfloat162_rn(
            wk[(size_t)(cb + 2*pp)     * 25 + k],
            wk[(size_t)(cb + 2*pp + 1) * 25 + k]);
        ws2[k][pp] = *reinterpret_cast<uint32_t*>(&pk);
    }
    if (tid < 128) bs[tid] = wb[cb + tid];
    __syncthreads();

    int grp = tid >> 4;                   // quad index (0..15)
    int oc  = tid & 15;                   // channel octet
    int token0 = blockIdx.x * 64 + grp * 4;
    int b = token0 >> 16;
    int p = token0 & 65535;
    int y = p >> 8, x0 = p & 255;         // tokens x0..x0+3, same row
    int ch = cb + oc * 8;
    const size_t rowbase = (size_t)(b * 65536 + y * 256);

    __nv_bfloat162 z = __float2bfloat162_rn(0.f);
    __nv_bfloat162 acc[4][4];
#pragma unroll
    for (int tk = 0; tk < 4; tk++)
#pragma unroll
        for (int j = 0; j < 4; j++) acc[tk][j] = z;
    uint4 cen[4];
#pragma unroll
    for (int tk = 0; tk < 4; tk++) cen[tk] = make_uint4(0u,0u,0u,0u);

#pragma unroll
    for (int dy = 0; dy < 5; dy++) {
        int yy = y + dy - 2;
        bool yok = (unsigned)yy < 256u;
        size_t rb = (size_t)(b * 65536 + yy * 256);
        uint4 col[8];
#pragma unroll
        for (int jx = 0; jx < 8; jx++) {
            int xc = x0 + jx - 2;
            uint4 v = make_uint4(0u, 0u, 0u, 0u);
            if (yok && (unsigned)xc < 256u)
                v = *(const uint4*)&h1[(rb + xc) * HID + ch];
            col[jx] = v;
        }
        if (dy == 2) {
#pragma unroll
            for (int tk = 0; tk < 4; tk++) cen[tk] = col[tk + 2];
        }
#pragma unroll
        for (int jx = 0; jx < 8; jx++) {
            const __nv_bfloat162* vp = reinterpret_cast<const __nv_bfloat162*>(&col[jx]);
#pragma unroll
            for (int tk = 0; tk < 4; tk++) {
                int tap = jx - tk;
                if (tap >= 0 && tap < 5) {
                    uint4 wv = *(const uint4*)&ws2[dy*5 + tap][oc*4];
                    const __nv_bfloat162* wp =
                        reinterpret_cast<const __nv_bfloat162*>(&wv);
#pragma unroll
                    for (int j = 0; j < 4; j++)
                        acc[tk][j] = __hfma2(vp[j], wp[j], acc[tk][j]);
                }
            }
        }
    }

#pragma unroll
    for (int tk = 0; tk < 4; tk++) {
        const __nv_bfloat162* cp = reinterpret_cast<const __nv_bfloat162*>(&cen[tk]);
        uint4 o;
        __nv_bfloat162* op2 = reinterpret_cast<__nv_bfloat162*>(&o);
#pragma unroll
        for (int j = 0; j < 4; j++) {
            float b0 = bs[oc*8 + 2*j], b1 = bs[oc*8 + 2*j + 1];
            float2 a = __bfloat1622float2(acc[tk][j]);
            float2 c = __bfloat1622float2(cp[j]);
            op2[j] = __float22bfloat162_rn(make_float2(c.x + gelu_f(a.x + b0),
                                                       c.y + gelu_f(a.y + b1)));
        }
        *(uint4*)&out[(rowbase + x0 + tk) * HID + ch] = o;
    }
}

// ---------------------------------------------------------------------------
// Launch sequence (graph-capturable: kernel launches only)
// ---------------------------------------------------------------------------
extern "C" void kernel_launch(void* const* d_in, const int* in_sizes, int n_in,
                              void* d_out, int out_size)
{
    const float* x    = (const float*)d_in[0];
    const float* g1   = (const float*)d_in[1];
    const float* be1  = (const float*)d_in[2];
    const float* wq   = (const float*)d_in[3];
    const float* bq   = (const float*)d_in[4];
    const float* wkv  = (const float*)d_in[5];
    const float* bkv  = (const float*)d_in[6];
    const float* btab = (const float*)d_in[7];
    const float* wproj= (const float*)d_in[8];
    const float* bproj= (const float*)d_in[9];
    const float* g2   = (const float*)d_in[10];
    const float* be2  = (const float*)d_in[11];
    const float* w1f  = (const float*)d_in[12];
    const float* b1f  = (const float*)d_in[13];
    const float* dwk  = (const float*)d_in[14];
    const float* dwb  = (const float*)d_in[15];
    const float* w2f  = (const float*)d_in[16];
    const float* b2f  = (const float*)d_in[17];
    float* out = (float*)d_out;

    __nv_bfloat16 *xn, *qkvb, *aw, *h1, *h, *wb;
    float *x2, *bqkv;
    cudaGetSymbolAddress((void**)&xn,   g_xn);
    cudaGetSymbolAddress((void**)&qkvb, g_qkvb);
    cudaGetSymbolAddress((void**)&aw,   g_aw);
    cudaGetSymbolAddress((void**)&x2,   g_x2);
    cudaGetSymbolAddress((void**)&h1,   g_h1);
    cudaGetSymbolAddress((void**)&h,    g_h);
    cudaGetSymbolAddress((void**)&wb,   g_wb);
    cudaGetSymbolAddress((void**)&bqkv, g_bqkv);

    const int smem64  = 3 * (128 * SA + 32 * 72)  * 2;   // 44544 B
    const int smem128 = 3 * (128 * SA + 32 * 136) * 2;   // 56832 B
    cudaFuncSetAttribute(gemm_bf16_kernel<128>,
                         cudaFuncAttributeMaxDynamicSharedMemorySize, smem128);

    // 0. Weight/bias prep (bf16, QKV concat)
    prep_kernel<<<(387072 + 255)/256, 256>>>(wq, wkv, wproj, w1f, w2f, wb,
                                             bq, bkv, bqkv);

    // 1. LN1 -> xn (bf16)
    ln_kernel<<<NTOK/8, 256>>>(x, g1, be1, xn);
    // 2. QKV = xn @ wqkv + bqkv  (bf16, ldc=288; BN=128 -> 3 n-blocks)
    gemm_bf16_kernel<128><<<dim3(3, NTOK/128), 256, smem128>>>(
        xn, 192, wb + WB_WQKV, 288, bqkv, qkvb, QKVLD, 288, 192, nullptr, 0, 1);
    // 3. Window attention -> aw (bf16, token order)
    attn_kernel<<<2048, 384>>>(qkvb, btab, aw);
    // 4. x2 = aw @ wproj + bproj + x  (fp32; BN=64 -> 3 n-blocks)
    gemm_bf16_kernel<64><<<dim3(3, NTOK/128), 256, smem64>>>(
        aw, 192, wb + WB_WPROJ, 192, bproj, x2, 192, 192, 192, x, 0, 0);
    // 5. LN2 -> xn (bf16)
    ln_kernel<<<NTOK/8, 256>>>(x2, g2, be2, xn);
    // 6. h1 = gelu(xn @ w1f + b1f)  (bf16; BN=128 -> 6 n-blocks)
    gemm_bf16_kernel<128><<<dim3(6, NTOK/128), 256, smem128>>>(
        xn, 192, wb + WB_W1F, HID, b1f, h1, HID, HID, 192, nullptr, 1, 1);
    // 7. h = h1 + gelu(dwconv(h1) + dwb)  (bf16, 4 tokens/thread)
    dwconv_kernel<<<dim3(NTOK/64, 6), 256>>>(h1, dwk, dwb, h);
    // 8. out = h @ w2f + b2f + x2  (fp32; BN=64 -> 3 n-blocks)
    gemm_bf16_kernel<64><<<dim3(3, NTOK/128), 256, smem64>>>(
        h, HID, wb + WB_W2F, 192, b2f, out, 192, 192, HID, x2, 0, 0);
}